// round 3
// baseline (speedup 1.0000x reference)
#include <cuda_runtime.h>
#include <math.h>
#include <float.h>

#define NEG_BIG (-3.402823466e38f)

constexpr int Bb = 2, TQn = 1024, TKn = 2048, DQn = 1024, DCn = 768, Hn = 16, DHn = 64;

// Scratch (allocation-free rule: __device__ globals), referenced only in device code.
__device__ float g_Q[Bb * Hn * TQn * DHn];   // (b,h,q,d)  8 MB
__device__ float g_K[Bb * Hn * TKn * DHn];   // (b,h,k,d) 16 MB
__device__ float g_V[Bb * Hn * TKn * DHn];   // (b,h,k,d) 16 MB
__device__ float g_AO[Bb * TQn * DQn];       // (b,q,h*64+d) 8 MB
__device__ int   g_mask_mode;                // 0=uint8, 1=int32, 2=float32

// ---------------------------------------------------------------------------
// Mask dtype detection: scan first 4096 bytes (valid under all interpretations).
//   any byte > 1                       -> float32 (1.0f has bytes 0x80, 0x3F)
//   any byte == 1 at pos % 4 != 0      -> uint8/bool
//   else                               -> int32
// ---------------------------------------------------------------------------
__global__ void detect_mask_kernel(const unsigned char* __restrict__ m)
{
    __shared__ int s_big, s_mis;
    if (threadIdx.x == 0) { s_big = 0; s_mis = 0; }
    __syncthreads();
    int big = 0, mis = 0;
    for (int i = threadIdx.x; i < Bb * TKn; i += 256) {
        unsigned char v = m[i];
        if (v > 1) big = 1;
        else if (v == 1 && (i & 3)) mis = 1;
    }
    if (big) atomicOr(&s_big, 1);
    if (mis) atomicOr(&s_mis, 1);
    __syncthreads();
    if (threadIdx.x == 0) g_mask_mode = s_big ? 2 : (s_mis ? 0 : 1);
}

// ---------------------------------------------------------------------------
// SGEMM: C = A(MxK) @ W(KxN) + bias.  BM=BN=128, BK=8, 256 thr, 8x8 micro,
// double-buffered shared memory.
// DST 0/1/2: scatter to head layout g_Q/g_K/g_V:  out[((b*H+h)*T+t)*64+d]
// DST 4:     A-source is g_AO (selected in DEVICE code), plain row-major out.
// ---------------------------------------------------------------------------
template <int DST>
__global__ __launch_bounds__(256, 2) void gemm_k(
    const float* __restrict__ A, const float* __restrict__ W,
    const float* __restrict__ bias, float* __restrict__ Cext,
    int M, int K, int N, int T)
{
    __shared__ float As[2][8][128];
    __shared__ float Bs[2][8][132];
    const int tid = threadIdx.x;
    const int tx = tid & 15, ty = tid >> 4;
    const int m0 = blockIdx.y * 128, n0 = blockIdx.x * 128;

    const float* Asrc = (DST == 4) ? (const float*)g_AO : A;   // device-side symbol ref

    float acc[8][8];
#pragma unroll
    for (int i = 0; i < 8; ++i)
#pragma unroll
        for (int j = 0; j < 8; ++j) acc[i][j] = 0.f;

    const int arow = tid >> 1, acol = (tid & 1) * 4;
    const int brow = tid >> 5, bcol = (tid & 31) * 4;
    const float* Ap = Asrc + (size_t)(m0 + arow) * K + acol;
    const float* Wp = W + (size_t)brow * N + n0 + bcol;

    // prologue: stage 0
    {
        float4 av = *(const float4*)(Ap);
        float4 bv = *(const float4*)(Wp);
        As[0][acol + 0][arow] = av.x;
        As[0][acol + 1][arow] = av.y;
        As[0][acol + 2][arow] = av.z;
        As[0][acol + 3][arow] = av.w;
        *(float4*)&Bs[0][brow][bcol] = bv;
    }
    __syncthreads();

    int buf = 0;
    for (int k0 = 0; k0 < K; k0 += 8) {
        float4 av, bv;
        const bool has_next = (k0 + 8) < K;
        if (has_next) {
            av = *(const float4*)(Ap + k0 + 8);
            bv = *(const float4*)(Wp + (size_t)(k0 + 8) * N);
        }
#pragma unroll
        for (int kk = 0; kk < 8; ++kk) {
            float4 a0 = *(const float4*)&As[buf][kk][ty * 8];
            float4 a1 = *(const float4*)&As[buf][kk][ty * 8 + 4];
            float4 b0 = *(const float4*)&Bs[buf][kk][tx * 8];
            float4 b1 = *(const float4*)&Bs[buf][kk][tx * 8 + 4];
            float ar[8] = {a0.x, a0.y, a0.z, a0.w, a1.x, a1.y, a1.z, a1.w};
            float br[8] = {b0.x, b0.y, b0.z, b0.w, b1.x, b1.y, b1.z, b1.w};
#pragma unroll
            for (int i = 0; i < 8; ++i)
#pragma unroll
                for (int j = 0; j < 8; ++j) acc[i][j] += ar[i] * br[j];
        }
        if (has_next) {
            const int nb = buf ^ 1;
            As[nb][acol + 0][arow] = av.x;
            As[nb][acol + 1][arow] = av.y;
            As[nb][acol + 2][arow] = av.z;
            As[nb][acol + 3][arow] = av.w;
            *(float4*)&Bs[nb][brow][bcol] = bv;
            __syncthreads();
            buf = nb;
        }
    }

#pragma unroll
    for (int i = 0; i < 8; ++i) {
        int r = m0 + ty * 8 + i;
#pragma unroll
        for (int j = 0; j < 8; ++j) {
            int c = n0 + tx * 8 + j;
            float v = acc[i][j] + bias[c];
            if (DST <= 2) {
                float* C = (DST == 0) ? g_Q : (DST == 1) ? g_K : g_V;
                int bb = r / T, tl = r - bb * T;
                int h = c >> 6, d = c & 63;
                C[((size_t)((bb * Hn + h) * T + tl) << 6) + d] = v;
            } else {
                Cext[(size_t)r * N + c] = v;
            }
        }
    }
}

// ---------------------------------------------------------------------------
// Attention with exact top-64 sparsification.
// CTA = 256 thr (8 warps) = 16 queries of one (b,h); 2 queries per warp.
// Per lane: 64 logit registers per query (4 keys/lane per 128-key tile x 16 tiles).
// ---------------------------------------------------------------------------
__device__ __forceinline__ int cnt_ge(const float (&a)[64], float t)
{
    int c = 0;
#pragma unroll
    for (int j = 0; j < 64; ++j) c += (a[j] >= t) ? 1 : 0;
    return __reduce_add_sync(0xffffffffu, c);
}

__device__ __forceinline__ void attend_out(float (&acc)[64], int lane,
                                           const float* __restrict__ Vb,
                                           float* __restrict__ outp)
{
    // row max (selected set always contains the max)
    float m = NEG_BIG;
#pragma unroll
    for (int j = 0; j < 64; ++j) m = fmaxf(m, acc[j]);
#pragma unroll
    for (int o = 16; o > 0; o >>= 1) m = fmaxf(m, __shfl_xor_sync(0xffffffffu, m, o));

    // bisection for the top-64 threshold; early-exit when count == 64
    float lo = m - 32.0f, hi = m;
    int cnt = cnt_ge(acc, lo);
    int guard = 0;
    while (cnt < 64 && guard++ < 90) { lo = m - 2.0f * (m - lo); cnt = cnt_ge(acc, lo); }
    for (int it = 0; it < 48 && cnt != 64; ++it) {
        float mid = 0.5f * (lo + hi);
        if (!(mid > lo && mid < hi)) break;
        int c2 = cnt_ge(acc, mid);
        if (c2 >= 64) { lo = mid; cnt = c2; } else { hi = mid; }
    }
    const float thr = lo;

    // softmax over selected + AV accumulation (lane d owns out dims d, d+32)
    float z = 0.f, o0 = 0.f, o1 = 0.f;
#pragma unroll
    for (int j = 0; j < 64; ++j) {
        unsigned bal = __ballot_sync(0xffffffffu, acc[j] >= thr);
        while (bal) {
            int src = __ffs(bal) - 1;
            bal &= bal - 1;
            float a = __shfl_sync(0xffffffffu, acc[j], src);
            float w = __expf(a - m);
            int key = ((j >> 2) << 7) + (src << 2) + (j & 3);
            z += w;
            o0 += w * Vb[key * 64 + lane];
            o1 += w * Vb[key * 64 + 32 + lane];
        }
    }
    float inv = 1.0f / z;
    outp[lane] = o0 * inv;
    outp[lane + 32] = o1 * inv;
}

__global__ __launch_bounds__(256, 1) void attn_k(const void* __restrict__ mask)
{
    __shared__ float KT[64][132];          // K tile transposed (d-major), padded
    __shared__ float qs[16][64];           // pre-scaled queries
    __shared__ unsigned char mk[TKn];

    const int b = blockIdx.z, h = blockIdx.y, q0 = blockIdx.x * 16;
    const int tid = threadIdx.x, lane = tid & 31, warp = tid >> 5;
    const float* Qb = g_Q + (size_t)((b * Hn + h) * TQn + q0) * 64;
    const float* Kb = g_K + (size_t)((b * Hn + h) * TKn) * 64;
    const float* Vb = g_V + (size_t)((b * Hn + h) * TKn) * 64;

    {   // load + scale q tile (fold 1/sqrt(64)=0.125, exact power of 2)
        int qi = tid >> 4, dc = (tid & 15) * 4;
        float4 v = *(const float4*)(Qb + qi * 64 + dc);
        qs[qi][dc + 0] = v.x * 0.125f;
        qs[qi][dc + 1] = v.y * 0.125f;
        qs[qi][dc + 2] = v.z * 0.125f;
        qs[qi][dc + 3] = v.w * 0.125f;
    }
    {   // mask load per detected dtype
        const int mode = g_mask_mode;
        if (mode == 2) {
            const float* mf = (const float*)mask;
            for (int i = tid; i < TKn; i += 256) mk[i] = (mf[b * TKn + i] != 0.f);
        } else if (mode == 1) {
            const int* mi = (const int*)mask;
            for (int i = tid; i < TKn; i += 256) mk[i] = (mi[b * TKn + i] != 0);
        } else {
            const unsigned char* m8 = (const unsigned char*)mask;
            for (int i = tid; i < TKn; i += 256) mk[i] = m8[b * TKn + i];
        }
    }

    float aA[64], aB[64];
#pragma unroll
    for (int j = 0; j < 64; ++j) { aA[j] = 0.f; aB[j] = 0.f; }

    const int qi0 = warp * 2, qi1 = qi0 + 1;
    const int dld = tid & 63, kld = (tid >> 6) * 32;   // transpose-loader assignment

#pragma unroll
    for (int t = 0; t < 16; ++t) {
        __syncthreads();
        // stage 128-key tile transposed: KT[d][k] = K[k][d]; global reads coalesced over d
        const float* Kt = Kb + (size_t)(t * 128 + kld) * 64 + dld;
#pragma unroll 8
        for (int j = 0; j < 32; ++j) KT[dld][kld + j] = Kt[(size_t)j * 64];
        __syncthreads();

        for (int dc = 0; dc < 64; dc += 8) {
            float qa[8], qb[8];
#pragma unroll
            for (int i = 0; i < 8; ++i) { qa[i] = qs[qi0][dc + i]; qb[i] = qs[qi1][dc + i]; }
#pragma unroll
            for (int i = 0; i < 8; ++i) {
                float4 kv = *(const float4*)&KT[dc + i][lane * 4];  // 16B smem -> 8 FMA
                aA[t * 4 + 0] += qa[i] * kv.x;
                aA[t * 4 + 1] += qa[i] * kv.y;
                aA[t * 4 + 2] += qa[i] * kv.z;
                aA[t * 4 + 3] += qa[i] * kv.w;
                aB[t * 4 + 0] += qb[i] * kv.x;
                aB[t * 4 + 1] += qb[i] * kv.y;
                aB[t * 4 + 2] += qb[i] * kv.z;
                aB[t * 4 + 3] += qb[i] * kv.w;
            }
        }
    }
    __syncthreads();

    // key padding mask -> finfo.min (matches reference exactly)
#pragma unroll
    for (int j = 0; j < 64; ++j) {
        int key = ((j >> 2) << 7) + (lane << 2) + (j & 3);
        if (mk[key]) { aA[j] = NEG_BIG; aB[j] = NEG_BIG; }
    }

    float* out0 = g_AO + (size_t)(b * TQn + q0 + qi0) * DQn + h * 64;
    float* out1 = g_AO + (size_t)(b * TQn + q0 + qi1) * DQn + h * 64;
    attend_out(aA, lane, Vb, out0);
    attend_out(aB, lane, Vb, out1);
}

// ---------------------------------------------------------------------------
extern "C" void kernel_launch(void* const* d_in, const int* in_sizes, int n_in,
                              void* d_out, int out_size)
{
    const float* x   = (const float*)d_in[0];   // (B,TQ,DQ)
    const float* ctx = (const float*)d_in[1];   // (B,TK,DC)
    const void*  msk = d_in[2];                 // (B,TK) bool-ish, dtype auto-detected
    const float* Wq = (const float*)d_in[3];
    const float* bq = (const float*)d_in[4];
    const float* Wk = (const float*)d_in[5];
    const float* bk = (const float*)d_in[6];
    const float* Wv = (const float*)d_in[7];
    const float* bv = (const float*)d_in[8];
    const float* Wo = (const float*)d_in[9];
    const float* bo = (const float*)d_in[10];
    float* out = (float*)d_out;

    dim3 blk(256);
    detect_mask_kernel<<<1, 256>>>((const unsigned char*)msk);
    // projections into head layouts (write g_Q/g_K/g_V directly)
    gemm_k<0><<<dim3(DQn / 128, (Bb * TQn) / 128), blk>>>(x,   Wq, bq, nullptr, Bb * TQn, DQn, DQn, TQn);
    gemm_k<1><<<dim3(DQn / 128, (Bb * TKn) / 128), blk>>>(ctx, Wk, bk, nullptr, Bb * TKn, DCn, DQn, TKn);
    gemm_k<2><<<dim3(DQn / 128, (Bb * TKn) / 128), blk>>>(ctx, Wv, bv, nullptr, Bb * TKn, DCn, DQn, TKn);
    // top-k attention (reads g_Q/g_K/g_V, writes g_AO)
    attn_k<<<dim3(TQn / 16, Hn, Bb), blk>>>(msk);
    // output projection (A-source = g_AO selected in device code)
    gemm_k<4><<<dim3(DQn / 128, (Bb * TQn) / 128), blk>>>(nullptr, Wo, bo, out, Bb * TQn, DQn, DQn, TQn);
}

// round 4
// speedup vs baseline: 1.4667x; 1.4667x over previous
#include <cuda_runtime.h>
#include <math.h>
#include <float.h>

#define NEG_BIG (-3.402823466e38f)

constexpr int Bb = 2, TQn = 1024, TKn = 2048, DQn = 1024, DCn = 768, Hn = 16, DHn = 64;

// Scratch (allocation-free rule: __device__ globals), referenced only in device code.
__device__ float g_Q[Bb * Hn * TQn * DHn];        // (b,h,q,d)   8 MB
__device__ float g_K[Bb * Hn * TKn * DHn];        // (b,h,k,d)  16 MB
__device__ float g_V[Bb * Hn * TKn * DHn];        // (b,h,k,d)  16 MB
__device__ float g_AO[Bb * TQn * DQn];            // (b,q,h*64+d) 8 MB
__device__ float g_L[(size_t)Bb * Hn * TQn * TKn]; // logits (bh,q,k) 256 MB
__device__ int   g_mask_mode;                     // 0=uint8, 1=int32, 2=float32

// ---------------- packed f32x2 helpers (sm_103a) ----------------
__device__ __forceinline__ unsigned long long pack2(float x) {
    unsigned long long r;
    asm("mov.b64 %0, {%1, %1};" : "=l"(r) : "f"(x));
    return r;
}
#define FFMA2(acc, a, b) \
    asm("fma.rn.f32x2 %0, %1, %2, %0;" : "+l"(acc) : "l"(a), "l"(b))
__device__ __forceinline__ void unpack2(unsigned long long v, float& lo, float& hi) {
    asm("mov.b64 {%0, %1}, %2;" : "=f"(lo), "=f"(hi) : "l"(v));
}

// ---------------------------------------------------------------------------
// Mask dtype detection (scan first B*TK bytes; safe under all interpretations).
// ---------------------------------------------------------------------------
__global__ void detect_mask_kernel(const unsigned char* __restrict__ m)
{
    __shared__ int s_big, s_mis;
    if (threadIdx.x == 0) { s_big = 0; s_mis = 0; }
    __syncthreads();
    int big = 0, mis = 0;
    for (int i = threadIdx.x; i < Bb * TKn; i += 256) {
        unsigned char v = m[i];
        if (v > 1) big = 1;
        else if (v == 1 && (i & 3)) mis = 1;
    }
    if (big) atomicOr(&s_big, 1);
    if (mis) atomicOr(&s_mis, 1);
    __syncthreads();
    if (threadIdx.x == 0) g_mask_mode = s_big ? 2 : (s_mis ? 0 : 1);
}

__device__ __forceinline__ unsigned char mask_at(const void* mask, int mode, int idx)
{
    if (mode == 2) return ((const float*)mask)[idx] != 0.f;
    if (mode == 1) return ((const int*)mask)[idx] != 0;
    return ((const unsigned char*)mask)[idx];
}

// ---------------------------------------------------------------------------
// SGEMM: C = A(MxK) @ W(KxN) + bias.  BM=BN=128, BK=8, 256 thr, 8x8 micro,
// double-buffered smem, packed f32x2 FMAs (bitwise == scalar fp32 chain).
// DST 0/1/2: scatter to head layout g_Q/g_K/g_V. DST 4: A-source g_AO, plain out.
// ---------------------------------------------------------------------------
template <int DST>
__global__ __launch_bounds__(256, 2) void gemm_k(
    const float* __restrict__ A, const float* __restrict__ W,
    const float* __restrict__ bias, float* __restrict__ Cext,
    int M, int K, int N, int T)
{
    __shared__ float As[2][8][128];
    __shared__ float Bs[2][8][132];
    const int tid = threadIdx.x;
    const int tx = tid & 15, ty = tid >> 4;
    const int m0 = blockIdx.y * 128, n0 = blockIdx.x * 128;

    const float* Asrc = (DST == 4) ? (const float*)g_AO : A;

    unsigned long long acc2[8][4];   // [row][col-pair], f32x2 packed
#pragma unroll
    for (int i = 0; i < 8; ++i)
#pragma unroll
        for (int jp = 0; jp < 4; ++jp) acc2[i][jp] = 0ull;

    const int arow = tid >> 1, acol = (tid & 1) * 4;
    const int brow = tid >> 5, bcol = (tid & 31) * 4;
    const float* Ap = Asrc + (size_t)(m0 + arow) * K + acol;
    const float* Wp = W + (size_t)brow * N + n0 + bcol;

    {   // prologue: stage 0
        float4 av = *(const float4*)(Ap);
        float4 bv = *(const float4*)(Wp);
        As[0][acol + 0][arow] = av.x;
        As[0][acol + 1][arow] = av.y;
        As[0][acol + 2][arow] = av.z;
        As[0][acol + 3][arow] = av.w;
        *(float4*)&Bs[0][brow][bcol] = bv;
    }
    __syncthreads();

    int buf = 0;
    for (int k0 = 0; k0 < K; k0 += 8) {
        float4 av, bv;
        const bool has_next = (k0 + 8) < K;
        if (has_next) {
            av = *(const float4*)(Ap + k0 + 8);
            bv = *(const float4*)(Wp + (size_t)(k0 + 8) * N);
        }
#pragma unroll
        for (int kk = 0; kk < 8; ++kk) {
            float4 a0 = *(const float4*)&As[buf][kk][ty * 8];
            float4 a1 = *(const float4*)&As[buf][kk][ty * 8 + 4];
            // B cols as b64 pairs straight from smem (16B aligned: 132*4 % 16 == 0)
            ulonglong2 b01 = *(const ulonglong2*)&Bs[buf][kk][tx * 8];
            ulonglong2 b23 = *(const ulonglong2*)&Bs[buf][kk][tx * 8 + 4];
            unsigned long long b2[4] = {b01.x, b01.y, b23.x, b23.y};
            float ar[8] = {a0.x, a0.y, a0.z, a0.w, a1.x, a1.y, a1.z, a1.w};
#pragma unroll
            for (int i = 0; i < 8; ++i) {
                unsigned long long pa = pack2(ar[i]);
#pragma unroll
                for (int jp = 0; jp < 4; ++jp) FFMA2(acc2[i][jp], pa, b2[jp]);
            }
        }
        if (has_next) {
            const int nb = buf ^ 1;
            As[nb][acol + 0][arow] = av.x;
            As[nb][acol + 1][arow] = av.y;
            As[nb][acol + 2][arow] = av.z;
            As[nb][acol + 3][arow] = av.w;
            *(float4*)&Bs[nb][brow][bcol] = bv;
            __syncthreads();
            buf = nb;
        }
    }

#pragma unroll
    for (int i = 0; i < 8; ++i) {
        int r = m0 + ty * 8 + i;
        float accf[8];
#pragma unroll
        for (int jp = 0; jp < 4; ++jp) unpack2(acc2[i][jp], accf[2 * jp], accf[2 * jp + 1]);
#pragma unroll
        for (int j = 0; j < 8; ++j) {
            int c = n0 + tx * 8 + j;
            float v = accf[j] + bias[c];
            if (DST <= 2) {
                float* C = (DST == 0) ? g_Q : (DST == 1) ? g_K : g_V;
                int bb = r / T, tl = r - bb * T;
                int h = c >> 6, d = c & 63;
                C[((size_t)((bb * Hn + h) * T + tl) << 6) + d] = v;
            } else {
                Cext[(size_t)r * N + c] = v;
            }
        }
    }
}

// ---------------------------------------------------------------------------
// QK^T logits GEMM: per (b,h), L[q][k] = (0.125*Q[q]) . K[k], masked -> NEG_BIG.
// Tiles 128q x 128k, K-depth 64 staged fully (transposed, conflict-free STS).
// Accumulation order identical to round-3 attn (ascending d, single FMA chain).
// ---------------------------------------------------------------------------
__global__ __launch_bounds__(256, 2) void qk_logits_k(const void* __restrict__ mask)
{
    extern __shared__ float sm[];
    float (*Qs)[132] = (float (*)[132])sm;            // [64 d][128 q + pad]
    float (*Ks)[132] = (float (*)[132])(sm + 64 * 132); // [64 d][128 k + pad]

    const int tid = threadIdx.x;
    const int bh = blockIdx.z;                 // b*16 + h
    const int q0 = blockIdx.y * 128, n0 = blockIdx.x * 128;
    const float* Qb = g_Q + ((size_t)bh * TQn + q0) * 64;
    const float* Kb = g_K + ((size_t)bh * TKn + n0) * 64;

    {   // stage both tiles transposed; lanes sweep m => conflict-free STS
        const int m = tid & 127, half = tid >> 7;
#pragma unroll
        for (int cc = 0; cc < 8; ++cc) {
            const int d4 = half + 2 * cc;         // 0..15
            float4 qv = *(const float4*)(Qb + (size_t)m * 64 + d4 * 4);
            Qs[d4 * 4 + 0][m] = qv.x * 0.125f;
            Qs[d4 * 4 + 1][m] = qv.y * 0.125f;
            Qs[d4 * 4 + 2][m] = qv.z * 0.125f;
            Qs[d4 * 4 + 3][m] = qv.w * 0.125f;
            float4 kv = *(const float4*)(Kb + (size_t)m * 64 + d4 * 4);
            Ks[d4 * 4 + 0][m] = kv.x;
            Ks[d4 * 4 + 1][m] = kv.y;
            Ks[d4 * 4 + 2][m] = kv.z;
            Ks[d4 * 4 + 3][m] = kv.w;
        }
    }
    __syncthreads();

    const int tx = tid & 15, ty = tid >> 4;
    float acc[8][8];
#pragma unroll
    for (int i = 0; i < 8; ++i)
#pragma unroll
        for (int j = 0; j < 8; ++j) acc[i][j] = 0.f;

#pragma unroll 8
    for (int kk = 0; kk < 64; ++kk) {
        float4 a0 = *(const float4*)&Qs[kk][ty * 8];
        float4 a1 = *(const float4*)&Qs[kk][ty * 8 + 4];
        float4 b0 = *(const float4*)&Ks[kk][tx * 8];
        float4 b1 = *(const float4*)&Ks[kk][tx * 8 + 4];
        float ar[8] = {a0.x, a0.y, a0.z, a0.w, a1.x, a1.y, a1.z, a1.w};
        float br[8] = {b0.x, b0.y, b0.z, b0.w, b1.x, b1.y, b1.z, b1.w};
#pragma unroll
        for (int i = 0; i < 8; ++i)
#pragma unroll
            for (int j = 0; j < 8; ++j) acc[i][j] += ar[i] * br[j];
    }

    // epilogue: mask -> NEG_BIG, store
    const int mode = g_mask_mode, b = bh >> 4;
    unsigned char mku[8];
#pragma unroll
    for (int j = 0; j < 8; ++j) mku[j] = mask_at(mask, mode, b * TKn + n0 + tx * 8 + j);

#pragma unroll
    for (int i = 0; i < 8; ++i) {
        float* Lp = g_L + ((size_t)bh * TQn + q0 + ty * 8 + i) * TKn + n0 + tx * 8;
        float o[8];
#pragma unroll
        for (int j = 0; j < 8; ++j) o[j] = mku[j] ? NEG_BIG : acc[i][j];
        *(float4*)(Lp) = make_float4(o[0], o[1], o[2], o[3]);
        *(float4*)(Lp + 4) = make_float4(o[4], o[5], o[6], o[7]);
    }
}

// ---------------------------------------------------------------------------
// Top-64 + softmax + sparse AV. Warp per query; lane j-strided logits.
// ---------------------------------------------------------------------------
__device__ __forceinline__ int cnt_ge(const float (&a)[64], float t)
{
    int c = 0;
#pragma unroll
    for (int j = 0; j < 64; ++j) c += (a[j] >= t) ? 1 : 0;
    return __reduce_add_sync(0xffffffffu, c);
}

__global__ __launch_bounds__(256, 2) void topk_av_k()
{
    const int lane = threadIdx.x & 31, w = threadIdx.x >> 5;
    const int b = blockIdx.z, h = blockIdx.y;
    const int bh = b * Hn + h;
    const int q = blockIdx.x * 8 + w;

    const float* Lq = g_L + ((size_t)bh * TQn + q) * TKn;
    float acc[64];
#pragma unroll
    for (int j = 0; j < 64; ++j) acc[j] = Lq[j * 32 + lane];

    // row max
    float m = NEG_BIG;
#pragma unroll
    for (int j = 0; j < 64; ++j) m = fmaxf(m, acc[j]);
#pragma unroll
    for (int o = 16; o > 0; o >>= 1) m = fmaxf(m, __shfl_xor_sync(0xffffffffu, m, o));

    // bisection for the top-64 threshold; early-exit when count == 64
    float lo = m - 32.0f, hi = m;
    int cnt = cnt_ge(acc, lo);
    int guard = 0;
    while (cnt < 64 && guard++ < 90) { lo = m - 2.0f * (m - lo); cnt = cnt_ge(acc, lo); }
    for (int it = 0; it < 48 && cnt != 64; ++it) {
        float mid = 0.5f * (lo + hi);
        if (!(mid > lo && mid < hi)) break;
        int c2 = cnt_ge(acc, mid);
        if (c2 >= 64) { lo = mid; cnt = c2; } else { hi = mid; }
    }
    const float thr = lo;

    // softmax over selected + AV (lane owns out dims lane, lane+32)
    const float* Vb = g_V + (size_t)bh * TKn * 64;
    float z = 0.f, o0 = 0.f, o1 = 0.f;
#pragma unroll
    for (int j = 0; j < 64; ++j) {
        unsigned bal = __ballot_sync(0xffffffffu, acc[j] >= thr);
        while (bal) {
            int src = __ffs(bal) - 1;
            bal &= bal - 1;
            float a = __shfl_sync(0xffffffffu, acc[j], src);
            float wgt = __expf(a - m);
            int key = j * 32 + src;
            z += wgt;
            o0 += wgt * Vb[(size_t)key * 64 + lane];
            o1 += wgt * Vb[(size_t)key * 64 + 32 + lane];
        }
    }
    float inv = 1.0f / z;
    float* op = g_AO + ((size_t)b * TQn + q) * DQn + h * 64;
    op[lane] = o0 * inv;
    op[lane + 32] = o1 * inv;
}

// ---------------------------------------------------------------------------
extern "C" void kernel_launch(void* const* d_in, const int* in_sizes, int n_in,
                              void* d_out, int out_size)
{
    const float* x   = (const float*)d_in[0];
    const float* ctx = (const float*)d_in[1];
    const void*  msk = d_in[2];
    const float* Wq = (const float*)d_in[3];
    const float* bq = (const float*)d_in[4];
    const float* Wk = (const float*)d_in[5];
    const float* bk = (const float*)d_in[6];
    const float* Wv = (const float*)d_in[7];
    const float* bv = (const float*)d_in[8];
    const float* Wo = (const float*)d_in[9];
    const float* bo = (const float*)d_in[10];
    float* out = (float*)d_out;

    static bool attr_done = false;
    const int qk_smem = 2 * 64 * 132 * sizeof(float);   // 67.6 KB
    if (!attr_done) {
        cudaFuncSetAttribute(qk_logits_k, cudaFuncAttributeMaxDynamicSharedMemorySize, qk_smem);
        attr_done = true;
    }

    dim3 blk(256);
    detect_mask_kernel<<<1, 256>>>((const unsigned char*)msk);
    // projections into head layouts
    gemm_k<0><<<dim3(DQn / 128, (Bb * TQn) / 128), blk>>>(x,   Wq, bq, nullptr, Bb * TQn, DQn, DQn, TQn);
    gemm_k<1><<<dim3(DQn / 128, (Bb * TKn) / 128), blk>>>(ctx, Wk, bk, nullptr, Bb * TKn, DCn, DQn, TKn);
    gemm_k<2><<<dim3(DQn / 128, (Bb * TKn) / 128), blk>>>(ctx, Wv, bv, nullptr, Bb * TKn, DCn, DQn, TKn);
    // masked logits
    qk_logits_k<<<dim3(TKn / 128, TQn / 128, Bb * Hn), blk, qk_smem>>>(msk);
    // top-64 + softmax + sparse AV
    topk_av_k<<<dim3(TQn / 8, Hn, Bb), blk>>>();
    // output projection
    gemm_k<4><<<dim3(DQn / 128, (Bb * TQn) / 128), blk>>>(nullptr, Wo, bo, out, Bb * TQn, DQn, DQn, TQn);
}

// round 5
// speedup vs baseline: 1.5702x; 1.0706x over previous
#include <cuda_runtime.h>
#include <math.h>
#include <float.h>

#define NEG_BIG (-3.402823466e38f)

constexpr int Bb = 2, TQn = 1024, TKn = 2048, DQn = 1024, DCn = 768, Hn = 16, DHn = 64;

// Scratch (allocation-free rule: __device__ globals), referenced only in device code.
__device__ float g_Q[Bb * Hn * TQn * DHn];        // (b,h,q,d)   8 MB
__device__ float g_K[Bb * Hn * TKn * DHn];        // (b,h,k,d)  16 MB
__device__ float g_V[Bb * Hn * TKn * DHn];        // (b,h,k,d)  16 MB
__device__ float g_AO[Bb * TQn * DQn];            // (b,q,h*64+d) 8 MB
__device__ float g_L[(size_t)Bb * Hn * TQn * TKn]; // logits (bh,q,k) 256 MB
__device__ int   g_mask_mode;                     // 0=uint8, 1=int32, 2=float32

// ---------------- packed f32x2 helpers (sm_103a) ----------------
__device__ __forceinline__ unsigned long long pack2(float x) {
    unsigned long long r;
    asm("mov.b64 %0, {%1, %1};" : "=l"(r) : "f"(x));
    return r;
}
#define FFMA2(acc, a, b) \
    asm("fma.rn.f32x2 %0, %1, %2, %0;" : "+l"(acc) : "l"(a), "l"(b))
__device__ __forceinline__ void unpack2(unsigned long long v, float& lo, float& hi) {
    asm("mov.b64 {%0, %1}, %2;" : "=f"(lo), "=f"(hi) : "l"(v));
}

// ---------------------------------------------------------------------------
// Mask dtype detection (scan first B*TK bytes; safe under all interpretations).
// ---------------------------------------------------------------------------
__global__ void detect_mask_kernel(const unsigned char* __restrict__ m)
{
    __shared__ int s_big, s_mis;
    if (threadIdx.x == 0) { s_big = 0; s_mis = 0; }
    __syncthreads();
    int big = 0, mis = 0;
    for (int i = threadIdx.x; i < Bb * TKn; i += 256) {
        unsigned char v = m[i];
        if (v > 1) big = 1;
        else if (v == 1 && (i & 3)) mis = 1;
    }
    if (big) atomicOr(&s_big, 1);
    if (mis) atomicOr(&s_mis, 1);
    __syncthreads();
    if (threadIdx.x == 0) g_mask_mode = s_big ? 2 : (s_mis ? 0 : 1);
}

__device__ __forceinline__ unsigned char mask_at(const void* mask, int mode, int idx)
{
    if (mode == 2) return ((const float*)mask)[idx] != 0.f;
    if (mode == 1) return ((const int*)mask)[idx] != 0;
    return ((const unsigned char*)mask)[idx];
}

// ---------------------------------------------------------------------------
// SGEMM: C = A(MxK) @ W(KxN) + bias.  BM=BN=128, BK=8, 256 thr, 8x8 micro,
// double-buffered smem, packed f32x2 FMAs (bitwise == scalar fp32 chain).
// DST 0/1/2: scatter to head layout g_Q/g_K/g_V. DST 4: A-source g_AO, plain out.
// ---------------------------------------------------------------------------
template <int DST>
__global__ __launch_bounds__(256, 2) void gemm_k(
    const float* __restrict__ A, const float* __restrict__ W,
    const float* __restrict__ bias, float* __restrict__ Cext,
    int M, int K, int N, int T)
{
    __shared__ float As[2][8][128];
    __shared__ float Bs[2][8][132];
    const int tid = threadIdx.x;
    const int tx = tid & 15, ty = tid >> 4;
    const int m0 = blockIdx.y * 128, n0 = blockIdx.x * 128;

    const float* Asrc = (DST == 4) ? (const float*)g_AO : A;

    unsigned long long acc2[8][4];   // [row][col-pair], f32x2 packed
#pragma unroll
    for (int i = 0; i < 8; ++i)
#pragma unroll
        for (int jp = 0; jp < 4; ++jp) acc2[i][jp] = 0ull;

    const int arow = tid >> 1, acol = (tid & 1) * 4;
    const int brow = tid >> 5, bcol = (tid & 31) * 4;
    const float* Ap = Asrc + (size_t)(m0 + arow) * K + acol;
    const float* Wp = W + (size_t)brow * N + n0 + bcol;

    {   // prologue: stage 0
        float4 av = *(const float4*)(Ap);
        float4 bv = *(const float4*)(Wp);
        As[0][acol + 0][arow] = av.x;
        As[0][acol + 1][arow] = av.y;
        As[0][acol + 2][arow] = av.z;
        As[0][acol + 3][arow] = av.w;
        *(float4*)&Bs[0][brow][bcol] = bv;
    }
    __syncthreads();

    int buf = 0;
    for (int k0 = 0; k0 < K; k0 += 8) {
        float4 av, bv;
        const bool has_next = (k0 + 8) < K;
        if (has_next) {
            av = *(const float4*)(Ap + k0 + 8);
            bv = *(const float4*)(Wp + (size_t)(k0 + 8) * N);
        }
#pragma unroll
        for (int kk = 0; kk < 8; ++kk) {
            float4 a0 = *(const float4*)&As[buf][kk][ty * 8];
            float4 a1 = *(const float4*)&As[buf][kk][ty * 8 + 4];
            ulonglong2 b01 = *(const ulonglong2*)&Bs[buf][kk][tx * 8];
            ulonglong2 b23 = *(const ulonglong2*)&Bs[buf][kk][tx * 8 + 4];
            unsigned long long b2[4] = {b01.x, b01.y, b23.x, b23.y};
            float ar[8] = {a0.x, a0.y, a0.z, a0.w, a1.x, a1.y, a1.z, a1.w};
#pragma unroll
            for (int i = 0; i < 8; ++i) {
                unsigned long long pa = pack2(ar[i]);
#pragma unroll
                for (int jp = 0; jp < 4; ++jp) FFMA2(acc2[i][jp], pa, b2[jp]);
            }
        }
        if (has_next) {
            const int nb = buf ^ 1;
            As[nb][acol + 0][arow] = av.x;
            As[nb][acol + 1][arow] = av.y;
            As[nb][acol + 2][arow] = av.z;
            As[nb][acol + 3][arow] = av.w;
            *(float4*)&Bs[nb][brow][bcol] = bv;
            __syncthreads();
            buf = nb;
        }
    }

#pragma unroll
    for (int i = 0; i < 8; ++i) {
        int r = m0 + ty * 8 + i;
        float accf[8];
#pragma unroll
        for (int jp = 0; jp < 4; ++jp) unpack2(acc2[i][jp], accf[2 * jp], accf[2 * jp + 1]);
#pragma unroll
        for (int j = 0; j < 8; ++j) {
            int c = n0 + tx * 8 + j;
            float v = accf[j] + bias[c];
            if (DST <= 2) {
                float* C = (DST == 0) ? g_Q : (DST == 1) ? g_K : g_V;
                int bb = r / T, tl = r - bb * T;
                int h = c >> 6, d = c & 63;
                C[((size_t)((bb * Hn + h) * T + tl) << 6) + d] = v;
            } else {
                Cext[(size_t)r * N + c] = v;
            }
        }
    }
}

// ---------------------------------------------------------------------------
// QK^T logits GEMM: per (b,h), L[q][k] = (0.125*Q[q]) . K[k], masked -> NEG_BIG.
// 128q x 128k tiles, full K-depth 64 staged transposed. Packed f32x2 FMAs with
// per-accumulator chains bitwise-identical to the scalar version (selection-safe).
// ---------------------------------------------------------------------------
__global__ __launch_bounds__(256, 2) void qk_logits_k(const void* __restrict__ mask)
{
    extern __shared__ float sm[];
    float (*Qs)[132] = (float (*)[132])sm;              // [64 d][128 q + pad]
    float (*Ks)[132] = (float (*)[132])(sm + 64 * 132); // [64 d][128 k + pad]

    const int tid = threadIdx.x;
    const int bh = blockIdx.z;                 // b*16 + h
    const int q0 = blockIdx.y * 128, n0 = blockIdx.x * 128;
    const float* Qb = g_Q + ((size_t)bh * TQn + q0) * 64;
    const float* Kb = g_K + ((size_t)bh * TKn + n0) * 64;

    {   // stage both tiles transposed; lanes sweep m => conflict-free STS
        const int m = tid & 127, half = tid >> 7;
#pragma unroll
        for (int cc = 0; cc < 8; ++cc) {
            const int d4 = half + 2 * cc;         // 0..15
            float4 qv = *(const float4*)(Qb + (size_t)m * 64 + d4 * 4);
            Qs[d4 * 4 + 0][m] = qv.x * 0.125f;
            Qs[d4 * 4 + 1][m] = qv.y * 0.125f;
            Qs[d4 * 4 + 2][m] = qv.z * 0.125f;
            Qs[d4 * 4 + 3][m] = qv.w * 0.125f;
            float4 kv = *(const float4*)(Kb + (size_t)m * 64 + d4 * 4);
            Ks[d4 * 4 + 0][m] = kv.x;
            Ks[d4 * 4 + 1][m] = kv.y;
            Ks[d4 * 4 + 2][m] = kv.z;
            Ks[d4 * 4 + 3][m] = kv.w;
        }
    }
    __syncthreads();

    const int tx = tid & 15, ty = tid >> 4;
    unsigned long long acc2[8][4];
#pragma unroll
    for (int i = 0; i < 8; ++i)
#pragma unroll
        for (int jp = 0; jp < 4; ++jp) acc2[i][jp] = 0ull;

#pragma unroll 8
    for (int kk = 0; kk < 64; ++kk) {
        float4 a0 = *(const float4*)&Qs[kk][ty * 8];
        float4 a1 = *(const float4*)&Qs[kk][ty * 8 + 4];
        ulonglong2 b01 = *(const ulonglong2*)&Ks[kk][tx * 8];
        ulonglong2 b23 = *(const ulonglong2*)&Ks[kk][tx * 8 + 4];
        unsigned long long b2[4] = {b01.x, b01.y, b23.x, b23.y};
        float ar[8] = {a0.x, a0.y, a0.z, a0.w, a1.x, a1.y, a1.z, a1.w};
#pragma unroll
        for (int i = 0; i < 8; ++i) {
            unsigned long long pa = pack2(ar[i]);
#pragma unroll
            for (int jp = 0; jp < 4; ++jp) FFMA2(acc2[i][jp], pa, b2[jp]);
        }
    }

    // epilogue: unpack, mask -> NEG_BIG, store
    const int mode = g_mask_mode, b = bh >> 4;
    unsigned char mku[8];
#pragma unroll
    for (int j = 0; j < 8; ++j) mku[j] = mask_at(mask, mode, b * TKn + n0 + tx * 8 + j);

#pragma unroll
    for (int i = 0; i < 8; ++i) {
        float* Lp = g_L + ((size_t)bh * TQn + q0 + ty * 8 + i) * TKn + n0 + tx * 8;
        float o[8];
#pragma unroll
        for (int jp = 0; jp < 4; ++jp) unpack2(acc2[i][jp], o[2 * jp], o[2 * jp + 1]);
#pragma unroll
        for (int j = 0; j < 8; ++j) if (mku[j]) o[j] = NEG_BIG;
        *(float4*)(Lp) = make_float4(o[0], o[1], o[2], o[3]);
        *(float4*)(Lp + 4) = make_float4(o[4], o[5], o[6], o[7]);
    }
}

// ---------------------------------------------------------------------------
// Top-64 + softmax + sparse AV. Warp per query.
// Lane owns contiguous 64-logit chunk (float4 loads). Selection via bisection
// (identical logits => identical selection as round 4), then ballot-prefix
// compaction to smem and a dense MLP-friendly AV loop.
// ---------------------------------------------------------------------------
__device__ __forceinline__ int cnt_ge(const float (&a)[64], float t)
{
    int c = 0;
#pragma unroll
    for (int j = 0; j < 64; ++j) c += (a[j] >= t) ? 1 : 0;
    return __reduce_add_sync(0xffffffffu, c);
}

__global__ __launch_bounds__(256, 2) void topk_av_k()
{
    __shared__ int   skey[8][80];
    __shared__ float swgt[8][80];

    const int lane = threadIdx.x & 31, w = threadIdx.x >> 5;
    const int b = blockIdx.z, h = blockIdx.y;
    const int bh = b * Hn + h;
    const int q = blockIdx.x * 8 + w;

    const float* Lq = g_L + ((size_t)bh * TQn + q) * TKn;
    float acc[64];
#pragma unroll
    for (int v4 = 0; v4 < 16; ++v4) {
        float4 t = *(const float4*)(Lq + lane * 64 + v4 * 4);
        acc[v4 * 4 + 0] = t.x; acc[v4 * 4 + 1] = t.y;
        acc[v4 * 4 + 2] = t.z; acc[v4 * 4 + 3] = t.w;
    }

    // row max
    float m = NEG_BIG;
#pragma unroll
    for (int j = 0; j < 64; ++j) m = fmaxf(m, acc[j]);
#pragma unroll
    for (int o = 16; o > 0; o >>= 1) m = fmaxf(m, __shfl_xor_sync(0xffffffffu, m, o));

    // bisection for the top-64 threshold; early-exit when count == 64
    float lo = m - 32.0f, hi = m;
    int cnt = cnt_ge(acc, lo);
    int guard = 0;
    while (cnt < 64 && guard++ < 90) { lo = m - 2.0f * (m - lo); cnt = cnt_ge(acc, lo); }
    for (int it = 0; it < 48 && cnt != 64; ++it) {
        float mid = 0.5f * (lo + hi);
        if (!(mid > lo && mid < hi)) break;
        int c2 = cnt_ge(acc, mid);
        if (c2 >= 64) { lo = mid; cnt = c2; } else { hi = mid; }
    }
    const float thr = lo;

    // ballot-prefix compaction of selected (key, exp(logit-m)) pairs
    int base = 0;
#pragma unroll
    for (int j = 0; j < 64; ++j) {
        bool sel = acc[j] >= thr;
        unsigned bal = __ballot_sync(0xffffffffu, sel);
        if (sel) {
            int pos = base + __popc(bal & ((1u << lane) - 1u));
            if (pos < 80) {
                skey[w][pos] = lane * 64 + j;
                swgt[w][pos] = __expf(acc[j] - m);
            }
        }
        base += __popc(bal);
    }
    const int nsel = base < 80 ? base : 80;
    __syncwarp();

    // z = sum of weights
    float z = 0.f;
    for (int i = lane; i < nsel; i += 32) z += swgt[w][i];
#pragma unroll
    for (int o = 16; o > 0; o >>= 1) z += __shfl_xor_sync(0xffffffffu, z, o);

    // dense AV: 8-way unroll => 16 LDGs in flight, latency hidden
    const float* Vb = g_V + (size_t)bh * TKn * 64;
    float o0 = 0.f, o1 = 0.f;
    int i = 0;
    for (; i + 8 <= nsel; i += 8) {
        int   kv[8]; float wv[8];
#pragma unroll
        for (int u = 0; u < 8; ++u) { kv[u] = skey[w][i + u]; wv[u] = swgt[w][i + u]; }
        float v0[8], v1[8];
#pragma unroll
        for (int u = 0; u < 8; ++u) {
            const float* vr = Vb + (size_t)kv[u] * 64;
            v0[u] = vr[lane];
            v1[u] = vr[lane + 32];
        }
#pragma unroll
        for (int u = 0; u < 8; ++u) { o0 += wv[u] * v0[u]; o1 += wv[u] * v1[u]; }
    }
    for (; i < nsel; ++i) {
        float wv = swgt[w][i];
        const float* vr = Vb + (size_t)skey[w][i] * 64;
        o0 += wv * vr[lane];
        o1 += wv * vr[lane + 32];
    }

    float inv = 1.0f / z;
    float* op = g_AO + ((size_t)b * TQn + q) * DQn + h * 64;
    op[lane] = o0 * inv;
    op[lane + 32] = o1 * inv;
}

// ---------------------------------------------------------------------------
extern "C" void kernel_launch(void* const* d_in, const int* in_sizes, int n_in,
                              void* d_out, int out_size)
{
    const float* x   = (const float*)d_in[0];
    const float* ctx = (const float*)d_in[1];
    const void*  msk = d_in[2];
    const float* Wq = (const float*)d_in[3];
    const float* bq = (const float*)d_in[4];
    const float* Wk = (const float*)d_in[5];
    const float* bk = (const float*)d_in[6];
    const float* Wv = (const float*)d_in[7];
    const float* bv = (const float*)d_in[8];
    const float* Wo = (const float*)d_in[9];
    const float* bo = (const float*)d_in[10];
    float* out = (float*)d_out;

    static bool attr_done = false;
    const int qk_smem = 2 * 64 * 132 * sizeof(float);   // 67.6 KB
    if (!attr_done) {
        cudaFuncSetAttribute(qk_logits_k, cudaFuncAttributeMaxDynamicSharedMemorySize, qk_smem);
        attr_done = true;
    }

    dim3 blk(256);
    detect_mask_kernel<<<1, 256>>>((const unsigned char*)msk);
    // projections into head layouts
    gemm_k<0><<<dim3(DQn / 128, (Bb * TQn) / 128), blk>>>(x,   Wq, bq, nullptr, Bb * TQn, DQn, DQn, TQn);
    gemm_k<1><<<dim3(DQn / 128, (Bb * TKn) / 128), blk>>>(ctx, Wk, bk, nullptr, Bb * TKn, DCn, DQn, TKn);
    gemm_k<2><<<dim3(DQn / 128, (Bb * TKn) / 128), blk>>>(ctx, Wv, bv, nullptr, Bb * TKn, DCn, DQn, TKn);
    // masked logits
    qk_logits_k<<<dim3(TKn / 128, TQn / 128, Bb * Hn), blk, qk_smem>>>(msk);
    // top-64 + softmax + sparse AV
    topk_av_k<<<dim3(TQn / 8, Hn, Bb), blk>>>();
    // output projection
    gemm_k<4><<<dim3(DQn / 128, (Bb * TQn) / 128), blk>>>(nullptr, Wo, bo, out, Bb * TQn, DQn, DQn, TQn);
}

// round 6
// speedup vs baseline: 1.6313x; 1.0389x over previous
#include <cuda_runtime.h>
#include <math.h>
#include <float.h>

#define NEG_BIG (-3.402823466e38f)

constexpr int Bb = 2, TQn = 1024, TKn = 2048, DQn = 1024, DCn = 768, Hn = 16, DHn = 64;

// Scratch (allocation-free rule: __device__ globals), referenced only in device code.
__device__ float g_Q[Bb * Hn * TQn * DHn];        // (b,h,q,d)   8 MB
__device__ float g_K[Bb * Hn * TKn * DHn];        // (b,h,k,d)  16 MB
__device__ float g_V[Bb * Hn * TKn * DHn];        // (b,h,k,d)  16 MB
__device__ float g_AO[Bb * TQn * DQn];            // (b,q,h*64+d) 8 MB
__device__ float g_L[(size_t)Bb * Hn * TQn * TKn]; // logits (bh,q,k) 256 MB
__device__ int   g_mask_mode;                     // 0=uint8, 1=int32, 2=float32

// ---------------- packed f32x2 helpers (sm_103a) ----------------
__device__ __forceinline__ unsigned long long pack2(float x) {
    unsigned long long r;
    asm("mov.b64 %0, {%1, %1};" : "=l"(r) : "f"(x));
    return r;
}
#define FFMA2(acc, a, b) \
    asm("fma.rn.f32x2 %0, %1, %2, %0;" : "+l"(acc) : "l"(a), "l"(b))
__device__ __forceinline__ void unpack2(unsigned long long v, float& lo, float& hi) {
    asm("mov.b64 {%0, %1}, %2;" : "=f"(lo), "=f"(hi) : "l"(v));
}

// ---------------------------------------------------------------------------
// Mask dtype detection (scan first B*TK bytes; safe under all interpretations).
// ---------------------------------------------------------------------------
__global__ void detect_mask_kernel(const unsigned char* __restrict__ m)
{
    __shared__ int s_big, s_mis;
    if (threadIdx.x == 0) { s_big = 0; s_mis = 0; }
    __syncthreads();
    int big = 0, mis = 0;
    for (int i = threadIdx.x; i < Bb * TKn; i += 256) {
        unsigned char v = m[i];
        if (v > 1) big = 1;
        else if (v == 1 && (i & 3)) mis = 1;
    }
    if (big) atomicOr(&s_big, 1);
    if (mis) atomicOr(&s_mis, 1);
    __syncthreads();
    if (threadIdx.x == 0) g_mask_mode = s_big ? 2 : (s_mis ? 0 : 1);
}

__device__ __forceinline__ unsigned char mask_at(const void* mask, int mode, int idx)
{
    if (mode == 2) return ((const float*)mask)[idx] != 0.f;
    if (mode == 1) return ((const int*)mask)[idx] != 0;
    return ((const unsigned char*)mask)[idx];
}

// ---------------------------------------------------------------------------
// SGEMM: C = A(MxK) @ W(KxN) + bias.  BM=BN=128, BK=8, 256 thr, 8x8 micro,
// double-buffered smem, packed f32x2 FMAs (bitwise == scalar fp32 chain).
// DST 0/1/2: scatter to head layout g_Q/g_K/g_V. DST 4: A-source g_AO, plain out.
// ---------------------------------------------------------------------------
template <int DST>
__global__ __launch_bounds__(256, 2) void gemm_k(
    const float* __restrict__ A, const float* __restrict__ W,
    const float* __restrict__ bias, float* __restrict__ Cext,
    int M, int K, int N, int T)
{
    __shared__ float As[2][8][128];
    __shared__ float Bs[2][8][132];
    const int tid = threadIdx.x;
    const int tx = tid & 15, ty = tid >> 4;
    const int m0 = blockIdx.y * 128, n0 = blockIdx.x * 128;

    const float* Asrc = (DST == 4) ? (const float*)g_AO : A;

    unsigned long long acc2[8][4];   // [row][col-pair], f32x2 packed
#pragma unroll
    for (int i = 0; i < 8; ++i)
#pragma unroll
        for (int jp = 0; jp < 4; ++jp) acc2[i][jp] = 0ull;

    const int arow = tid >> 1, acol = (tid & 1) * 4;
    const int brow = tid >> 5, bcol = (tid & 31) * 4;
    const float* Ap = Asrc + (size_t)(m0 + arow) * K + acol;
    const float* Wp = W + (size_t)brow * N + n0 + bcol;

    {   // prologue: stage 0
        float4 av = *(const float4*)(Ap);
        float4 bv = *(const float4*)(Wp);
        As[0][acol + 0][arow] = av.x;
        As[0][acol + 1][arow] = av.y;
        As[0][acol + 2][arow] = av.z;
        As[0][acol + 3][arow] = av.w;
        *(float4*)&Bs[0][brow][bcol] = bv;
    }
    __syncthreads();

    int buf = 0;
    for (int k0 = 0; k0 < K; k0 += 8) {
        float4 av, bv;
        const bool has_next = (k0 + 8) < K;
        if (has_next) {
            av = *(const float4*)(Ap + k0 + 8);
            bv = *(const float4*)(Wp + (size_t)(k0 + 8) * N);
        }
#pragma unroll
        for (int kk = 0; kk < 8; ++kk) {
            float4 a0 = *(const float4*)&As[buf][kk][ty * 8];
            float4 a1 = *(const float4*)&As[buf][kk][ty * 8 + 4];
            ulonglong2 b01 = *(const ulonglong2*)&Bs[buf][kk][tx * 8];
            ulonglong2 b23 = *(const ulonglong2*)&Bs[buf][kk][tx * 8 + 4];
            unsigned long long b2[4] = {b01.x, b01.y, b23.x, b23.y};
            float ar[8] = {a0.x, a0.y, a0.z, a0.w, a1.x, a1.y, a1.z, a1.w};
#pragma unroll
            for (int i = 0; i < 8; ++i) {
                unsigned long long pa = pack2(ar[i]);
#pragma unroll
                for (int jp = 0; jp < 4; ++jp) FFMA2(acc2[i][jp], pa, b2[jp]);
            }
        }
        if (has_next) {
            const int nb = buf ^ 1;
            As[nb][acol + 0][arow] = av.x;
            As[nb][acol + 1][arow] = av.y;
            As[nb][acol + 2][arow] = av.z;
            As[nb][acol + 3][arow] = av.w;
            *(float4*)&Bs[nb][brow][bcol] = bv;
            __syncthreads();
            buf = nb;
        }
    }

#pragma unroll
    for (int i = 0; i < 8; ++i) {
        int r = m0 + ty * 8 + i;
        float accf[8];
#pragma unroll
        for (int jp = 0; jp < 4; ++jp) unpack2(acc2[i][jp], accf[2 * jp], accf[2 * jp + 1]);
#pragma unroll
        for (int j = 0; j < 8; ++j) {
            int c = n0 + tx * 8 + j;
            float v = accf[j] + bias[c];
            if (DST <= 2) {
                float* C = (DST == 0) ? g_Q : (DST == 1) ? g_K : g_V;
                int bb = r / T, tl = r - bb * T;
                int h = c >> 6, d = c & 63;
                C[((size_t)((bb * Hn + h) * T + tl) << 6) + d] = v;
            } else {
                Cext[(size_t)r * N + c] = v;
            }
        }
    }
}

// ---------------------------------------------------------------------------
// QK^T logits GEMM: per (b,h), L[q][k] = (0.125*Q[q]) . K[k], masked -> NEG_BIG.
// 128q x 128k tiles, full K-depth 64 staged transposed. Packed f32x2 FMAs with
// per-accumulator chains bitwise-identical to the scalar version (selection-safe).
// Logit stores use evict-first (.cs): 256MB stream, consumed once by topk_av.
// ---------------------------------------------------------------------------
__global__ __launch_bounds__(256, 2) void qk_logits_k(const void* __restrict__ mask)
{
    extern __shared__ float sm[];
    float (*Qs)[132] = (float (*)[132])sm;              // [64 d][128 q + pad]
    float (*Ks)[132] = (float (*)[132])(sm + 64 * 132); // [64 d][128 k + pad]

    const int tid = threadIdx.x;
    const int bh = blockIdx.z;                 // b*16 + h
    const int q0 = blockIdx.y * 128, n0 = blockIdx.x * 128;
    const float* Qb = g_Q + ((size_t)bh * TQn + q0) * 64;
    const float* Kb = g_K + ((size_t)bh * TKn + n0) * 64;

    {   // stage both tiles transposed; lanes sweep m => conflict-free STS
        const int m = tid & 127, half = tid >> 7;
#pragma unroll
        for (int cc = 0; cc < 8; ++cc) {
            const int d4 = half + 2 * cc;         // 0..15
            float4 qv = *(const float4*)(Qb + (size_t)m * 64 + d4 * 4);
            Qs[d4 * 4 + 0][m] = qv.x * 0.125f;
            Qs[d4 * 4 + 1][m] = qv.y * 0.125f;
            Qs[d4 * 4 + 2][m] = qv.z * 0.125f;
            Qs[d4 * 4 + 3][m] = qv.w * 0.125f;
            float4 kv = *(const float4*)(Kb + (size_t)m * 64 + d4 * 4);
            Ks[d4 * 4 + 0][m] = kv.x;
            Ks[d4 * 4 + 1][m] = kv.y;
            Ks[d4 * 4 + 2][m] = kv.z;
            Ks[d4 * 4 + 3][m] = kv.w;
        }
    }
    __syncthreads();

    const int tx = tid & 15, ty = tid >> 4;
    unsigned long long acc2[8][4];
#pragma unroll
    for (int i = 0; i < 8; ++i)
#pragma unroll
        for (int jp = 0; jp < 4; ++jp) acc2[i][jp] = 0ull;

#pragma unroll 8
    for (int kk = 0; kk < 64; ++kk) {
        float4 a0 = *(const float4*)&Qs[kk][ty * 8];
        float4 a1 = *(const float4*)&Qs[kk][ty * 8 + 4];
        ulonglong2 b01 = *(const ulonglong2*)&Ks[kk][tx * 8];
        ulonglong2 b23 = *(const ulonglong2*)&Ks[kk][tx * 8 + 4];
        unsigned long long b2[4] = {b01.x, b01.y, b23.x, b23.y};
        float ar[8] = {a0.x, a0.y, a0.z, a0.w, a1.x, a1.y, a1.z, a1.w};
#pragma unroll
        for (int i = 0; i < 8; ++i) {
            unsigned long long pa = pack2(ar[i]);
#pragma unroll
            for (int jp = 0; jp < 4; ++jp) FFMA2(acc2[i][jp], pa, b2[jp]);
        }
    }

    // epilogue: unpack, mask -> NEG_BIG, store (evict-first)
    const int mode = g_mask_mode, b = bh >> 4;
    unsigned char mku[8];
#pragma unroll
    for (int j = 0; j < 8; ++j) mku[j] = mask_at(mask, mode, b * TKn + n0 + tx * 8 + j);

#pragma unroll
    for (int i = 0; i < 8; ++i) {
        float* Lp = g_L + ((size_t)bh * TQn + q0 + ty * 8 + i) * TKn + n0 + tx * 8;
        float o[8];
#pragma unroll
        for (int jp = 0; jp < 4; ++jp) unpack2(acc2[i][jp], o[2 * jp], o[2 * jp + 1]);
#pragma unroll
        for (int j = 0; j < 8; ++j) if (mku[j]) o[j] = NEG_BIG;
        __stcs((float4*)Lp,       make_float4(o[0], o[1], o[2], o[3]));
        __stcs((float4*)(Lp + 4), make_float4(o[4], o[5], o[6], o[7]));
    }
}

// ---------------------------------------------------------------------------
// Top-64 + softmax + sparse AV. Warp per query.
// Lane-strided logit loads (j*32+lane): fully coalesced, evict-first, deep MLP.
// Selection identical to prior rounds (same per-warp value set -> same counts
// -> same bisection threshold). Compaction + dense AV for latency hiding.
// ---------------------------------------------------------------------------
__device__ __forceinline__ int cnt_ge(const float (&a)[64], float t)
{
    int c = 0;
#pragma unroll
    for (int j = 0; j < 64; ++j) c += (a[j] >= t) ? 1 : 0;
    return __reduce_add_sync(0xffffffffu, c);
}

__global__ __launch_bounds__(256, 2) void topk_av_k()
{
    __shared__ int   skey[8][80];
    __shared__ float swgt[8][80];

    const int lane = threadIdx.x & 31, w = threadIdx.x >> 5;
    const int b = blockIdx.z, h = blockIdx.y;
    const int bh = b * Hn + h;
    const int q = blockIdx.x * 8 + w;

    const float* Lq = g_L + ((size_t)bh * TQn + q) * TKn;
    float acc[64];
#pragma unroll
    for (int j = 0; j < 64; ++j) acc[j] = __ldcs(Lq + j * 32 + lane);

    // row max
    float m = NEG_BIG;
#pragma unroll
    for (int j = 0; j < 64; ++j) m = fmaxf(m, acc[j]);
#pragma unroll
    for (int o = 16; o > 0; o >>= 1) m = fmaxf(m, __shfl_xor_sync(0xffffffffu, m, o));

    // bisection for the top-64 threshold; early-exit when count == 64
    float lo = m - 32.0f, hi = m;
    int cnt = cnt_ge(acc, lo);
    int guard = 0;
    while (cnt < 64 && guard++ < 90) { lo = m - 2.0f * (m - lo); cnt = cnt_ge(acc, lo); }
    for (int it = 0; it < 48 && cnt != 64; ++it) {
        float mid = 0.5f * (lo + hi);
        if (!(mid > lo && mid < hi)) break;
        int c2 = cnt_ge(acc, mid);
        if (c2 >= 64) { lo = mid; cnt = c2; } else { hi = mid; }
    }
    const float thr = lo;

    // ballot-prefix compaction of selected (key, exp(logit-m)) pairs
    int base = 0;
#pragma unroll
    for (int j = 0; j < 64; ++j) {
        bool sel = acc[j] >= thr;
        unsigned bal = __ballot_sync(0xffffffffu, sel);
        if (sel) {
            int pos = base + __popc(bal & ((1u << lane) - 1u));
            if (pos < 80) {
                skey[w][pos] = j * 32 + lane;
                swgt[w][pos] = __expf(acc[j] - m);
            }
        }
        base += __popc(bal);
    }
    const int nsel = base < 80 ? base : 80;
    __syncwarp();

    // z = sum of weights
    float z = 0.f;
    for (int i = lane; i < nsel; i += 32) z += swgt[w][i];
#pragma unroll
    for (int o = 16; o > 0; o >>= 1) z += __shfl_xor_sync(0xffffffffu, z, o);

    // dense AV: 8-way unroll => 16 LDGs in flight, latency hidden
    const float* Vb = g_V + (size_t)bh * TKn * 64;
    float o0 = 0.f, o1 = 0.f;
    int i = 0;
    for (; i + 8 <= nsel; i += 8) {
        int   kv[8]; float wv[8];
#pragma unroll
        for (int u = 0; u < 8; ++u) { kv[u] = skey[w][i + u]; wv[u] = swgt[w][i + u]; }
        float v0[8], v1[8];
#pragma unroll
        for (int u = 0; u < 8; ++u) {
            const float* vr = Vb + (size_t)kv[u] * 64;
            v0[u] = vr[lane];
            v1[u] = vr[lane + 32];
        }
#pragma unroll
        for (int u = 0; u < 8; ++u) { o0 += wv[u] * v0[u]; o1 += wv[u] * v1[u]; }
    }
    for (; i < nsel; ++i) {
        float wv = swgt[w][i];
        const float* vr = Vb + (size_t)skey[w][i] * 64;
        o0 += wv * vr[lane];
        o1 += wv * vr[lane + 32];
    }

    float inv = 1.0f / z;
    float* op = g_AO + ((size_t)b * TQn + q) * DQn + h * 64;
    op[lane] = o0 * inv;
    op[lane + 32] = o1 * inv;
}

// ---------------------------------------------------------------------------
extern "C" void kernel_launch(void* const* d_in, const int* in_sizes, int n_in,
                              void* d_out, int out_size)
{
    const float* x   = (const float*)d_in[0];
    const float* ctx = (const float*)d_in[1];
    const void*  msk = d_in[2];
    const float* Wq = (const float*)d_in[3];
    const float* bq = (const float*)d_in[4];
    const float* Wk = (const float*)d_in[5];
    const float* bk = (const float*)d_in[6];
    const float* Wv = (const float*)d_in[7];
    const float* bv = (const float*)d_in[8];
    const float* Wo = (const float*)d_in[9];
    const float* bo = (const float*)d_in[10];
    float* out = (float*)d_out;

    static bool attr_done = false;
    const int qk_smem = 2 * 64 * 132 * sizeof(float);   // 67.6 KB
    if (!attr_done) {
        cudaFuncSetAttribute(qk_logits_k, cudaFuncAttributeMaxDynamicSharedMemorySize, qk_smem);
        attr_done = true;
    }

    dim3 blk(256);
    detect_mask_kernel<<<1, 256>>>((const unsigned char*)msk);
    // projections into head layouts
    gemm_k<0><<<dim3(DQn / 128, (Bb * TQn) / 128), blk>>>(x,   Wq, bq, nullptr, Bb * TQn, DQn, DQn, TQn);
    gemm_k<1><<<dim3(DQn / 128, (Bb * TKn) / 128), blk>>>(ctx, Wk, bk, nullptr, Bb * TKn, DCn, DQn, TKn);
    gemm_k<2><<<dim3(DQn / 128, (Bb * TKn) / 128), blk>>>(ctx, Wv, bv, nullptr, Bb * TKn, DCn, DQn, TKn);
    // masked logits
    qk_logits_k<<<dim3(TKn / 128, TQn / 128, Bb * Hn), blk, qk_smem>>>(msk);
    // top-64 + softmax + sparse AV
    topk_av_k<<<dim3(TQn / 8, Hn, Bb), blk>>>();
    // output projection
    gemm_k<4><<<dim3(DQn / 128, (Bb * TQn) / 128), blk>>>(nullptr, Wo, bo, out, Bb * TQn, DQn, DQn, TQn);
}

// round 10
// speedup vs baseline: 1.6810x; 1.0305x over previous
#include <cuda_runtime.h>
#include <cuda_bf16.h>
#include <mma.h>
#include <math.h>
#include <float.h>

using namespace nvcuda;

#define NEG_BIG (-3.402823466e38f)

constexpr int Bb = 2, TQn = 1024, TKn = 2048, DQn = 1024, DCn = 768, Hn = 16, DHn = 64;

// Scratch (allocation-free rule: __device__ globals), referenced only in device code.
__device__ float g_Q[Bb * Hn * TQn * DHn];          // (b,h,q,d)   8 MB
__device__ float g_K[Bb * Hn * TKn * DHn];          // (b,h,k,d)  16 MB
__device__ float g_V[Bb * Hn * TKn * DHn];          // (b,h,k,d)  16 MB
__device__ float g_AO[Bb * TQn * DQn];              // (b,q,h*64+d) 8 MB
__device__ float g_L[(size_t)Bb * Hn * TQn * TKn];  // logits 256 MB
__device__ int   g_mask_mode;
// bf16x2 split planes (V / out projections only — selection-independent)
__device__ __nv_bfloat16 g_Asp[2ull * 4096 * 1024];     // activation splits
__device__ __nv_bfloat16 g_Ws[2][2ull * 1024 * 1024];   // transposed weight splits [n][k]: 0=Wv, 1=Wo

// ---------------- packed f32x2 helpers ----------------
__device__ __forceinline__ unsigned long long pack2(float x) {
    unsigned long long r; asm("mov.b64 %0, {%1, %1};" : "=l"(r) : "f"(x)); return r;
}
#define FFMA2(acc, a, b) asm("fma.rn.f32x2 %0, %1, %2, %0;" : "+l"(acc) : "l"(a), "l"(b))
__device__ __forceinline__ void unpack2(unsigned long long v, float& lo, float& hi) {
    asm("mov.b64 {%0, %1}, %2;" : "=f"(lo), "=f"(hi) : "l"(v));
}

// ---------------------------------------------------------------------------
// Mask dtype detection
// ---------------------------------------------------------------------------
__global__ void detect_mask_kernel(const unsigned char* __restrict__ m)
{
    __shared__ int s_big, s_mis;
    if (threadIdx.x == 0) { s_big = 0; s_mis = 0; }
    __syncthreads();
    int big = 0, mis = 0;
    for (int i = threadIdx.x; i < Bb * TKn; i += 256) {
        unsigned char v = m[i];
        if (v > 1) big = 1;
        else if (v == 1 && (i & 3)) mis = 1;
    }
    if (big) atomicOr(&s_big, 1);
    if (mis) atomicOr(&s_mis, 1);
    __syncthreads();
    if (threadIdx.x == 0) g_mask_mode = s_big ? 2 : (s_mis ? 0 : 1);
}

__device__ __forceinline__ unsigned char mask_at(const void* mask, int mode, int idx)
{
    if (mode == 2) return ((const float*)mask)[idx] != 0.f;
    if (mode == 1) return ((const int*)mask)[idx] != 0;
    return ((const unsigned char*)mask)[idx];
}

// ---------------------------------------------------------------------------
// fp32 SGEMM (round-6 proven): C = A @ W + bias. BM=BN=128, BK=8, 256 thr,
// 8x8 micro, double-buffered, packed f32x2 (bitwise == scalar fp32 chains).
// DST 0: head-scatter g_Q; DST 1: head-scatter g_K.
// ---------------------------------------------------------------------------
template <int DST>
__global__ __launch_bounds__(256, 2) void gemm_k(
    const float* __restrict__ A, const float* __restrict__ W,
    const float* __restrict__ bias, int M, int K, int N, int T)
{
    __shared__ float As[2][8][128];
    __shared__ float Bs[2][8][132];
    const int tid = threadIdx.x;
    const int tx = tid & 15, ty = tid >> 4;
    const int m0 = blockIdx.y * 128, n0 = blockIdx.x * 128;

    unsigned long long acc2[8][4];
#pragma unroll
    for (int i = 0; i < 8; ++i)
#pragma unroll
        for (int jp = 0; jp < 4; ++jp) acc2[i][jp] = 0ull;

    const int arow = tid >> 1, acol = (tid & 1) * 4;
    const int brow = tid >> 5, bcol = (tid & 31) * 4;
    const float* Ap = A + (size_t)(m0 + arow) * K + acol;
    const float* Wp = W + (size_t)brow * N + n0 + bcol;

    {
        float4 av = *(const float4*)(Ap);
        float4 bv = *(const float4*)(Wp);
        As[0][acol + 0][arow] = av.x;
        As[0][acol + 1][arow] = av.y;
        As[0][acol + 2][arow] = av.z;
        As[0][acol + 3][arow] = av.w;
        *(float4*)&Bs[0][brow][bcol] = bv;
    }
    __syncthreads();

    int buf = 0;
    for (int k0 = 0; k0 < K; k0 += 8) {
        float4 av, bv;
        const bool has_next = (k0 + 8) < K;
        if (has_next) {
            av = *(const float4*)(Ap + k0 + 8);
            bv = *(const float4*)(Wp + (size_t)(k0 + 8) * N);
        }
#pragma unroll
        for (int kk = 0; kk < 8; ++kk) {
            float4 a0 = *(const float4*)&As[buf][kk][ty * 8];
            float4 a1 = *(const float4*)&As[buf][kk][ty * 8 + 4];
            ulonglong2 b01 = *(const ulonglong2*)&Bs[buf][kk][tx * 8];
            ulonglong2 b23 = *(const ulonglong2*)&Bs[buf][kk][tx * 8 + 4];
            unsigned long long b2[4] = {b01.x, b01.y, b23.x, b23.y};
            float ar[8] = {a0.x, a0.y, a0.z, a0.w, a1.x, a1.y, a1.z, a1.w};
#pragma unroll
            for (int i = 0; i < 8; ++i) {
                unsigned long long pa = pack2(ar[i]);
#pragma unroll
                for (int jp = 0; jp < 4; ++jp) FFMA2(acc2[i][jp], pa, b2[jp]);
            }
        }
        if (has_next) {
            const int nb = buf ^ 1;
            As[nb][acol + 0][arow] = av.x;
            As[nb][acol + 1][arow] = av.y;
            As[nb][acol + 2][arow] = av.z;
            As[nb][acol + 3][arow] = av.w;
            *(float4*)&Bs[nb][brow][bcol] = bv;
            __syncthreads();
            buf = nb;
        }
    }

#pragma unroll
    for (int i = 0; i < 8; ++i) {
        int r = m0 + ty * 8 + i;
        float accf[8];
#pragma unroll
        for (int jp = 0; jp < 4; ++jp) unpack2(acc2[i][jp], accf[2 * jp], accf[2 * jp + 1]);
#pragma unroll
        for (int j = 0; j < 8; ++j) {
            int c = n0 + tx * 8 + j;
            float v = accf[j] + bias[c];
            float* C = (DST == 0) ? g_Q : g_K;
            int bb = r / T, tl = r - bb * T;
            int h = c >> 6, d = c & 63;
            C[((size_t)((bb * Hn + h) * T + tl) << 6) + d] = v;
        }
    }
}

// ---------------------------------------------------------------------------
// bf16x2 split of activations: A -> 2 bf16 planes in g_Asp (stride MK).
// SRC 0: external pointer; SRC 1: g_AO.
// ---------------------------------------------------------------------------
template <int SRC>
__global__ void split_A_k(const float* __restrict__ Aext, size_t MK)
{
    const float* A = (SRC == 1) ? (const float*)g_AO : Aext;
    for (size_t i = ((size_t)blockIdx.x * 256 + threadIdx.x) * 2; i < MK;
         i += (size_t)gridDim.x * 512) {
        float2 f = *(const float2*)(A + i);
        __nv_bfloat16 ax1 = __float2bfloat16(f.x);
        __nv_bfloat16 ax2 = __float2bfloat16(f.x - __bfloat162float(ax1));
        __nv_bfloat16 ay1 = __float2bfloat16(f.y);
        __nv_bfloat16 ay2 = __float2bfloat16(f.y - __bfloat162float(ay1));
        *(__nv_bfloat162*)(g_Asp + i)      = __nv_bfloat162(ax1, ay1);
        *(__nv_bfloat162*)(g_Asp + MK + i) = __nv_bfloat162(ax2, ay2);
    }
}

// ---------------------------------------------------------------------------
// W split + transpose: W[K][1024] f32 -> g_Ws[WIDX] 2 bf16 planes [1024][K].
// ---------------------------------------------------------------------------
template <int WIDX>
__global__ void split_W_k(const float* __restrict__ W, int K)
{
    __shared__ float t[32][33];
    const int k0 = blockIdx.y * 32, n0 = blockIdx.x * 32;
    const int tx = threadIdx.x, ty = threadIdx.y;   // (32, 8)
#pragma unroll
    for (int i = 0; i < 4; ++i)
        t[ty + 8 * i][tx] = W[(size_t)(k0 + ty + 8 * i) * 1024 + n0 + tx];
    __syncthreads();
    __nv_bfloat16* P = g_Ws[WIDX];
    const size_t NK = (size_t)1024 * K;
#pragma unroll
    for (int i = 0; i < 4; ++i) {
        int n = ty + 8 * i;
        float f = t[tx][n];                          // = W[k0+tx][n0+n]
        __nv_bfloat16 b1 = __float2bfloat16(f);
        __nv_bfloat16 b2 = __float2bfloat16(f - __bfloat162float(b1));
        size_t o = (size_t)(n0 + n) * K + k0 + tx;
        P[o] = b1; P[NK + o] = b2;
    }
}

// ---------------------------------------------------------------------------
// wmma bf16x2 GEMM: C[M,1024] = A @ W + bias via 3 split products
// (A1B1 + A1B2 + A2B1) folded into one extended-K loop. Tile 128m x 64n x 32k,
// 8 warps (4m x 2n), HMMA m16n16k16 bf16->f32, double-buffered smem.
// DST 2: head-scatter to g_V; DST 4: plain out.
// ---------------------------------------------------------------------------
template <int DST>
__global__ __launch_bounds__(256, 2) void wmma_gemm(
    const float* __restrict__ bias, float* __restrict__ Cext, int M, int K, int T)
{
    // A: 2 bufs x [128][40] bf16 (10240B); B: 2 bufs x [64][40] (5120B)
    __shared__ __align__(16) unsigned char smraw[30720];
    __shared__ float sbias[64];

    const int tid = threadIdx.x, wid = tid >> 5;
    const int wm = wid & 3, wn = wid >> 2;
    const int n0 = blockIdx.x * 64, m0 = blockIdx.y * 128;

    auto Arow = [&](int buf, int r) -> __nv_bfloat16* {
        return (__nv_bfloat16*)(smraw + buf * 10240 + r * 80);
    };
    auto Brow = [&](int buf, int r) -> __nv_bfloat16* {
        return (__nv_bfloat16*)(smraw + 20480 + buf * 5120 + r * 80);
    };

    if (tid < 64) sbias[tid] = bias[n0 + tid];

    const int WIDX = (DST == 2) ? 0 : 1;
    const __nv_bfloat16* Wt = g_Ws[WIDX];
    const size_t MK = (size_t)M * K, NK = (size_t)1024 * K;
    const int kch = K >> 5, nch = 3 * kch;
    const int PA[3] = {0, 0, 1};
    const int PB[3] = {0, 1, 0};

    wmma::fragment<wmma::accumulator, 16, 16, 16, float> acc[2][2];
#pragma unroll
    for (int i = 0; i < 2; ++i)
#pragma unroll
        for (int j = 0; j < 2; ++j) wmma::fill_fragment(acc[i][j], 0.f);

    {   // prologue: chunk 0 (planes A0/B0, ko=0)
        const __nv_bfloat16* gA = g_Asp + (size_t)m0 * K;
        const __nv_bfloat16* gB = Wt + (size_t)n0 * K;
#pragma unroll
        for (int u = 0; u < 2; ++u) {
            int idx = u * 256 + tid, row = idx >> 2, c8 = idx & 3;
            uint4 v = *(const uint4*)(gA + (size_t)row * K + c8 * 8);
            *(uint4*)(Arow(0, row) + c8 * 8) = v;
        }
        {
            int row = tid >> 2, c8 = tid & 3;
            uint4 v = *(const uint4*)(gB + (size_t)row * K + c8 * 8);
            *(uint4*)(Brow(0, row) + c8 * 8) = v;
        }
    }
    __syncthreads();

    int buf = 0;
    for (int c = 0; c < nch; ++c) {
        uint4 va0, va1, vb;
        const bool has_next = (c + 1) < nch;
        if (has_next) {
            const int cn = c + 1, sub = cn / kch, ko = (cn - sub * kch) << 5;
            const __nv_bfloat16* gA = g_Asp + (size_t)PA[sub] * MK + (size_t)m0 * K + ko;
            const __nv_bfloat16* gB = Wt + (size_t)PB[sub] * NK + (size_t)n0 * K + ko;
            {
                int i0 = tid, r = i0 >> 2, c8 = i0 & 3;
                va0 = *(const uint4*)(gA + (size_t)r * K + c8 * 8);
            }
            {
                int i1 = 256 + tid, r = i1 >> 2, c8 = i1 & 3;
                va1 = *(const uint4*)(gA + (size_t)r * K + c8 * 8);
            }
            {
                int r = tid >> 2, c8 = tid & 3;
                vb = *(const uint4*)(gB + (size_t)r * K + c8 * 8);
            }
        }

#pragma unroll
        for (int ks = 0; ks < 2; ++ks) {
            wmma::fragment<wmma::matrix_a, 16, 16, 16, __nv_bfloat16, wmma::row_major> af[2];
            wmma::fragment<wmma::matrix_b, 16, 16, 16, __nv_bfloat16, wmma::col_major> bf[2];
#pragma unroll
            for (int mi = 0; mi < 2; ++mi)
                wmma::load_matrix_sync(af[mi], Arow(buf, wm * 32 + mi * 16) + ks * 16, 40);
#pragma unroll
            for (int ni = 0; ni < 2; ++ni)
                wmma::load_matrix_sync(bf[ni], Brow(buf, wn * 32 + ni * 16) + ks * 16, 40);
#pragma unroll
            for (int mi = 0; mi < 2; ++mi)
#pragma unroll
                for (int ni = 0; ni < 2; ++ni)
                    wmma::mma_sync(acc[mi][ni], af[mi], bf[ni], acc[mi][ni]);
        }

        if (has_next) {
            const int nb = buf ^ 1;
            {
                int i0 = tid, r = i0 >> 2, c8 = i0 & 3;
                *(uint4*)(Arow(nb, r) + c8 * 8) = va0;
            }
            {
                int i1 = 256 + tid, r = i1 >> 2, c8 = i1 & 3;
                *(uint4*)(Arow(nb, r) + c8 * 8) = va1;
            }
            {
                int r = tid >> 2, c8 = tid & 3;
                *(uint4*)(Brow(nb, r) + c8 * 8) = vb;
            }
            __syncthreads();
            buf = nb;
        }
    }

    // epilogue: two half-passes through smem (reuse smraw as float [128][36])
    float (*Cs)[36] = (float (*)[36])smraw;
    const int r = tid >> 1, hc = (tid & 1) * 16;
    const int m = m0 + r;
    float* dst;
    if (DST == 2) {
        int bb = m / T, tl = m - bb * T, h = n0 >> 6;
        dst = g_V + ((size_t)((bb * Hn + h) * T + tl) << 6);
    } else {
        dst = Cext + (size_t)m * 1024 + n0;
    }

#pragma unroll
    for (int p = 0; p < 2; ++p) {
        __syncthreads();
        if (wn == p) {
#pragma unroll
            for (int mi = 0; mi < 2; ++mi)
#pragma unroll
                for (int ni = 0; ni < 2; ++ni)
                    wmma::store_matrix_sync(&Cs[wm * 32 + mi * 16][ni * 16],
                                            acc[mi][ni], 36, wmma::mem_row_major);
        }
        __syncthreads();
#pragma unroll
        for (int j4 = 0; j4 < 4; ++j4) {
            int cc = hc + j4 * 4;
            float4 v;
            v.x = Cs[r][cc + 0] + sbias[p * 32 + cc + 0];
            v.y = Cs[r][cc + 1] + sbias[p * 32 + cc + 1];
            v.z = Cs[r][cc + 2] + sbias[p * 32 + cc + 2];
            v.w = Cs[r][cc + 3] + sbias[p * 32 + cc + 3];
            *(float4*)(dst + p * 32 + cc) = v;
        }
    }
}

// ---------------------------------------------------------------------------
// QK^T logits GEMM (bitwise-identical to rounds 4-6)
// ---------------------------------------------------------------------------
__global__ __launch_bounds__(256, 2) void qk_logits_k(const void* __restrict__ mask)
{
    extern __shared__ float sm[];
    float (*Qs)[132] = (float (*)[132])sm;
    float (*Ks)[132] = (float (*)[132])(sm + 64 * 132);

    const int tid = threadIdx.x;
    const int bh = blockIdx.z;
    const int q0 = blockIdx.y * 128, n0 = blockIdx.x * 128;
    const float* Qb = g_Q + ((size_t)bh * TQn + q0) * 64;
    const float* Kb = g_K + ((size_t)bh * TKn + n0) * 64;

    {
        const int m = tid & 127, half = tid >> 7;
#pragma unroll
        for (int cc = 0; cc < 8; ++cc) {
            const int d4 = half + 2 * cc;
            float4 qv = *(const float4*)(Qb + (size_t)m * 64 + d4 * 4);
            Qs[d4 * 4 + 0][m] = qv.x * 0.125f;
            Qs[d4 * 4 + 1][m] = qv.y * 0.125f;
            Qs[d4 * 4 + 2][m] = qv.z * 0.125f;
            Qs[d4 * 4 + 3][m] = qv.w * 0.125f;
            float4 kv = *(const float4*)(Kb + (size_t)m * 64 + d4 * 4);
            Ks[d4 * 4 + 0][m] = kv.x;
            Ks[d4 * 4 + 1][m] = kv.y;
            Ks[d4 * 4 + 2][m] = kv.z;
            Ks[d4 * 4 + 3][m] = kv.w;
        }
    }
    __syncthreads();

    const int tx = tid & 15, ty = tid >> 4;
    unsigned long long acc2[8][4];
#pragma unroll
    for (int i = 0; i < 8; ++i)
#pragma unroll
        for (int jp = 0; jp < 4; ++jp) acc2[i][jp] = 0ull;

#pragma unroll 8
    for (int kk = 0; kk < 64; ++kk) {
        float4 a0 = *(const float4*)&Qs[kk][ty * 8];
        float4 a1 = *(const float4*)&Qs[kk][ty * 8 + 4];
        ulonglong2 b01 = *(const ulonglong2*)&Ks[kk][tx * 8];
        ulonglong2 b23 = *(const ulonglong2*)&Ks[kk][tx * 8 + 4];
        unsigned long long b2[4] = {b01.x, b01.y, b23.x, b23.y};
        float ar[8] = {a0.x, a0.y, a0.z, a0.w, a1.x, a1.y, a1.z, a1.w};
#pragma unroll
        for (int i = 0; i < 8; ++i) {
            unsigned long long pa = pack2(ar[i]);
#pragma unroll
            for (int jp = 0; jp < 4; ++jp) FFMA2(acc2[i][jp], pa, b2[jp]);
        }
    }

    const int mode = g_mask_mode, b = bh >> 4;
    unsigned char mku[8];
#pragma unroll
    for (int j = 0; j < 8; ++j) mku[j] = mask_at(mask, mode, b * TKn + n0 + tx * 8 + j);

#pragma unroll
    for (int i = 0; i < 8; ++i) {
        float* Lp = g_L + ((size_t)bh * TQn + q0 + ty * 8 + i) * TKn + n0 + tx * 8;
        float o[8];
#pragma unroll
        for (int jp = 0; jp < 4; ++jp) unpack2(acc2[i][jp], o[2 * jp], o[2 * jp + 1]);
#pragma unroll
        for (int j = 0; j < 8; ++j) if (mku[j]) o[j] = NEG_BIG;
        __stcs((float4*)Lp,       make_float4(o[0], o[1], o[2], o[3]));
        __stcs((float4*)(Lp + 4), make_float4(o[4], o[5], o[6], o[7]));
    }
}

// ---------------------------------------------------------------------------
// Top-64 + softmax + sparse AV (unchanged)
// ---------------------------------------------------------------------------
__device__ __forceinline__ int cnt_ge(const float (&a)[64], float t)
{
    int c = 0;
#pragma unroll
    for (int j = 0; j < 64; ++j) c += (a[j] >= t) ? 1 : 0;
    return __reduce_add_sync(0xffffffffu, c);
}

__global__ __launch_bounds__(256, 2) void topk_av_k()
{
    __shared__ int   skey[8][80];
    __shared__ float swgt[8][80];

    const int lane = threadIdx.x & 31, w = threadIdx.x >> 5;
    const int b = blockIdx.z, h = blockIdx.y;
    const int bh = b * Hn + h;
    const int q = blockIdx.x * 8 + w;

    const float* Lq = g_L + ((size_t)bh * TQn + q) * TKn;
    float acc[64];
#pragma unroll
    for (int j = 0; j < 64; ++j) acc[j] = __ldcs(Lq + j * 32 + lane);

    float m = NEG_BIG;
#pragma unroll
    for (int j = 0; j < 64; ++j) m = fmaxf(m, acc[j]);
#pragma unroll
    for (int o = 16; o > 0; o >>= 1) m = fmaxf(m, __shfl_xor_sync(0xffffffffu, m, o));

    float lo = m - 32.0f, hi = m;
    int cnt = cnt_ge(acc, lo);
    int guard = 0;
    while (cnt < 64 && guard++ < 90) { lo = m - 2.0f * (m - lo); cnt = cnt_ge(acc, lo); }
    for (int it = 0; it < 48 && cnt != 64; ++it) {
        float mid = 0.5f * (lo + hi);
        if (!(mid > lo && mid < hi)) break;
        int c2 = cnt_ge(acc, mid);
        if (c2 >= 64) { lo = mid; cnt = c2; } else { hi = mid; }
    }
    const float thr = lo;

    int base = 0;
#pragma unroll
    for (int j = 0; j < 64; ++j) {
        bool sel = acc[j] >= thr;
        unsigned bal = __ballot_sync(0xffffffffu, sel);
        if (sel) {
            int pos = base + __popc(bal & ((1u << lane) - 1u));
            if (pos < 80) {
                skey[w][pos] = j * 32 + lane;
                swgt[w][pos] = __expf(acc[j] - m);
            }
        }
        base += __popc(bal);
    }
    const int nsel = base < 80 ? base : 80;
    __syncwarp();

    float z = 0.f;
    for (int i = lane; i < nsel; i += 32) z += swgt[w][i];
#pragma unroll
    for (int o = 16; o > 0; o >>= 1) z += __shfl_xor_sync(0xffffffffu, z, o);

    const float* Vb = g_V + (size_t)bh * TKn * 64;
    float o0 = 0.f, o1 = 0.f;
    int i = 0;
    for (; i + 8 <= nsel; i += 8) {
        int   kv[8]; float wv[8];
#pragma unroll
        for (int u = 0; u < 8; ++u) { kv[u] = skey[w][i + u]; wv[u] = swgt[w][i + u]; }
        float v0[8], v1[8];
#pragma unroll
        for (int u = 0; u < 8; ++u) {
            const float* vr = Vb + (size_t)kv[u] * 64;
            v0[u] = vr[lane];
            v1[u] = vr[lane + 32];
        }
#pragma unroll
        for (int u = 0; u < 8; ++u) { o0 += wv[u] * v0[u]; o1 += wv[u] * v1[u]; }
    }
    for (; i < nsel; ++i) {
        float wv = swgt[w][i];
        const float* vr = Vb + (size_t)skey[w][i] * 64;
        o0 += wv * vr[lane];
        o1 += wv * vr[lane + 32];
    }

    float inv = 1.0f / z;
    float* op = g_AO + ((size_t)b * TQn + q) * DQn + h * 64;
    op[lane] = o0 * inv;
    op[lane + 32] = o1 * inv;
}

// ---------------------------------------------------------------------------
extern "C" void kernel_launch(void* const* d_in, const int* in_sizes, int n_in,
                              void* d_out, int out_size)
{
    const float* x   = (const float*)d_in[0];
    const float* ctx = (const float*)d_in[1];
    const void*  msk = d_in[2];
    const float* Wq = (const float*)d_in[3];
    const float* bq = (const float*)d_in[4];
    const float* Wk = (const float*)d_in[5];
    const float* bk = (const float*)d_in[6];
    const float* Wv = (const float*)d_in[7];
    const float* bv = (const float*)d_in[8];
    const float* Wo = (const float*)d_in[9];
    const float* bo = (const float*)d_in[10];
    float* out = (float*)d_out;

    const int qk_smem = 2 * 64 * 132 * sizeof(float);   // 67.6 KB
    static bool attr_done = false;
    if (!attr_done) {
        cudaFuncSetAttribute(qk_logits_k, cudaFuncAttributeMaxDynamicSharedMemorySize, qk_smem);
        attr_done = true;
    }

    detect_mask_kernel<<<1, 256>>>((const unsigned char*)msk);

    // Q, K projections: exact fp32 path (selection-critical)
    gemm_k<0><<<dim3(DQn / 128, (Bb * TQn) / 128), 256>>>(x,   Wq, bq, Bb * TQn, DQn, DQn, TQn);
    gemm_k<1><<<dim3(DQn / 128, (Bb * TKn) / 128), 256>>>(ctx, Wk, bk, Bb * TKn, DCn, DQn, TKn);

    // V projection: wmma bf16x2 (selection-independent)
    split_W_k<0><<<dim3(32, 24), dim3(32, 8)>>>(Wv, 768);
    split_W_k<1><<<dim3(32, 32), dim3(32, 8)>>>(Wo, 1024);
    split_A_k<0><<<4096, 256>>>(ctx, (size_t)4096 * 768);
    wmma_gemm<2><<<dim3(16, 32), 256>>>(bv, nullptr, 4096, 768, 2048);

    // masked logits (bitwise-identical to round 6)
    qk_logits_k<<<dim3(TKn / 128, TQn / 128, Bb * Hn), 256, qk_smem>>>(msk);
    // top-64 + softmax + sparse AV
    topk_av_k<<<dim3(TQn / 8, Hn, Bb), 256>>>();

    // output projection: wmma bf16x2
    split_A_k<1><<<4096, 256>>>(nullptr, (size_t)2048 * 1024);
    wmma_gemm<4><<<dim3(16, 16), 256>>>(bo, out, 2048, 1024, 1024);
}

// round 11
// speedup vs baseline: 1.7301x; 1.0292x over previous
#include <cuda_runtime.h>
#include <cuda_bf16.h>
#include <mma.h>
#include <math.h>
#include <float.h>

using namespace nvcuda;

#define NEG_BIG (-3.402823466e38f)

constexpr int Bb = 2, TQn = 1024, TKn = 2048, DQn = 1024, DCn = 768, Hn = 16, DHn = 64;

// Scratch (allocation-free rule: __device__ globals), referenced only in device code.
__device__ float g_Q[Bb * Hn * TQn * DHn];          // (b,h,q,d)   8 MB
__device__ float g_K[Bb * Hn * TKn * DHn];          // (b,h,k,d)  16 MB
__device__ float g_V[Bb * Hn * TKn * DHn];          // (b,h,k,d)  16 MB
__device__ float g_L[(size_t)Bb * Hn * TQn * TKn];  // logits 256 MB
__device__ int   g_mask_mode;
// bf16x2 split planes (V / out projections only — selection-independent)
__device__ __nv_bfloat16 g_Asp[2ull * 4096 * 1024];     // activation splits
__device__ __nv_bfloat16 g_Ws[2][2ull * 1024 * 1024];   // transposed weight splits [n][k]: 0=Wv, 1=Wo

// ---------------- packed f32x2 helpers ----------------
__device__ __forceinline__ unsigned long long pack2(float x) {
    unsigned long long r; asm("mov.b64 %0, {%1, %1};" : "=l"(r) : "f"(x)); return r;
}
#define FFMA2(acc, a, b) asm("fma.rn.f32x2 %0, %1, %2, %0;" : "+l"(acc) : "l"(a), "l"(b))
__device__ __forceinline__ void unpack2(unsigned long long v, float& lo, float& hi) {
    asm("mov.b64 {%0, %1}, %2;" : "=f"(lo), "=f"(hi) : "l"(v));
}

// ---------------------------------------------------------------------------
// Mask dtype detection
// ---------------------------------------------------------------------------
__global__ void detect_mask_kernel(const unsigned char* __restrict__ m)
{
    __shared__ int s_big, s_mis;
    if (threadIdx.x == 0) { s_big = 0; s_mis = 0; }
    __syncthreads();
    int big = 0, mis = 0;
    for (int i = threadIdx.x; i < Bb * TKn; i += 256) {
        unsigned char v = m[i];
        if (v > 1) big = 1;
        else if (v == 1 && (i & 3)) mis = 1;
    }
    if (big) atomicOr(&s_big, 1);
    if (mis) atomicOr(&s_mis, 1);
    __syncthreads();
    if (threadIdx.x == 0) g_mask_mode = s_big ? 2 : (s_mis ? 0 : 1);
}

__device__ __forceinline__ unsigned char mask_at(const void* mask, int mode, int idx)
{
    if (mode == 2) return ((const float*)mask)[idx] != 0.f;
    if (mode == 1) return ((const int*)mask)[idx] != 0;
    return ((const unsigned char*)mask)[idx];
}

// ---------------------------------------------------------------------------
// fp32 SGEMM (round-6 proven): C = A @ W + bias. BM=BN=128, BK=8, 256 thr,
// 8x8 micro, double-buffered, packed f32x2 (bitwise == scalar fp32 chains).
// DST 0: head-scatter g_Q; DST 1: head-scatter g_K.
// ---------------------------------------------------------------------------
template <int DST>
__global__ __launch_bounds__(256, 2) void gemm_k(
    const float* __restrict__ A, const float* __restrict__ W,
    const float* __restrict__ bias, int M, int K, int N, int T)
{
    __shared__ float As[2][8][128];
    __shared__ float Bs[2][8][132];
    const int tid = threadIdx.x;
    const int tx = tid & 15, ty = tid >> 4;
    const int m0 = blockIdx.y * 128, n0 = blockIdx.x * 128;

    unsigned long long acc2[8][4];
#pragma unroll
    for (int i = 0; i < 8; ++i)
#pragma unroll
        for (int jp = 0; jp < 4; ++jp) acc2[i][jp] = 0ull;

    const int arow = tid >> 1, acol = (tid & 1) * 4;
    const int brow = tid >> 5, bcol = (tid & 31) * 4;
    const float* Ap = A + (size_t)(m0 + arow) * K + acol;
    const float* Wp = W + (size_t)brow * N + n0 + bcol;

    {
        float4 av = *(const float4*)(Ap);
        float4 bv = *(const float4*)(Wp);
        As[0][acol + 0][arow] = av.x;
        As[0][acol + 1][arow] = av.y;
        As[0][acol + 2][arow] = av.z;
        As[0][acol + 3][arow] = av.w;
        *(float4*)&Bs[0][brow][bcol] = bv;
    }
    __syncthreads();

    int buf = 0;
    for (int k0 = 0; k0 < K; k0 += 8) {
        float4 av, bv;
        const bool has_next = (k0 + 8) < K;
        if (has_next) {
            av = *(const float4*)(Ap + k0 + 8);
            bv = *(const float4*)(Wp + (size_t)(k0 + 8) * N);
        }
#pragma unroll
        for (int kk = 0; kk < 8; ++kk) {
            float4 a0 = *(const float4*)&As[buf][kk][ty * 8];
            float4 a1 = *(const float4*)&As[buf][kk][ty * 8 + 4];
            ulonglong2 b01 = *(const ulonglong2*)&Bs[buf][kk][tx * 8];
            ulonglong2 b23 = *(const ulonglong2*)&Bs[buf][kk][tx * 8 + 4];
            unsigned long long b2[4] = {b01.x, b01.y, b23.x, b23.y};
            float ar[8] = {a0.x, a0.y, a0.z, a0.w, a1.x, a1.y, a1.z, a1.w};
#pragma unroll
            for (int i = 0; i < 8; ++i) {
                unsigned long long pa = pack2(ar[i]);
#pragma unroll
                for (int jp = 0; jp < 4; ++jp) FFMA2(acc2[i][jp], pa, b2[jp]);
            }
        }
        if (has_next) {
            const int nb = buf ^ 1;
            As[nb][acol + 0][arow] = av.x;
            As[nb][acol + 1][arow] = av.y;
            As[nb][acol + 2][arow] = av.z;
            As[nb][acol + 3][arow] = av.w;
            *(float4*)&Bs[nb][brow][bcol] = bv;
            __syncthreads();
            buf = nb;
        }
    }

#pragma unroll
    for (int i = 0; i < 8; ++i) {
        int r = m0 + ty * 8 + i;
        float accf[8];
#pragma unroll
        for (int jp = 0; jp < 4; ++jp) unpack2(acc2[i][jp], accf[2 * jp], accf[2 * jp + 1]);
#pragma unroll
        for (int j = 0; j < 8; ++j) {
            int c = n0 + tx * 8 + j;
            float v = accf[j] + bias[c];
            float* C = (DST == 0) ? g_Q : g_K;
            int bb = r / T, tl = r - bb * T;
            int h = c >> 6, d = c & 63;
            C[((size_t)((bb * Hn + h) * T + tl) << 6) + d] = v;
        }
    }
}

// ---------------------------------------------------------------------------
// bf16x2 split of ctx activations: A -> 2 bf16 planes in g_Asp (stride MK).
// ---------------------------------------------------------------------------
__global__ void split_A_k(const float* __restrict__ A, size_t MK)
{
    for (size_t i = ((size_t)blockIdx.x * 256 + threadIdx.x) * 2; i < MK;
         i += (size_t)gridDim.x * 512) {
        float2 f = *(const float2*)(A + i);
        __nv_bfloat16 ax1 = __float2bfloat16(f.x);
        __nv_bfloat16 ax2 = __float2bfloat16(f.x - __bfloat162float(ax1));
        __nv_bfloat16 ay1 = __float2bfloat16(f.y);
        __nv_bfloat16 ay2 = __float2bfloat16(f.y - __bfloat162float(ay1));
        *(__nv_bfloat162*)(g_Asp + i)      = __nv_bfloat162(ax1, ay1);
        *(__nv_bfloat162*)(g_Asp + MK + i) = __nv_bfloat162(ax2, ay2);
    }
}

// ---------------------------------------------------------------------------
// W split + transpose: W[K][1024] f32 -> g_Ws[WIDX] 2 bf16 planes [1024][K].
// ---------------------------------------------------------------------------
template <int WIDX>
__global__ void split_W_k(const float* __restrict__ W, int K)
{
    __shared__ float t[32][33];
    const int k0 = blockIdx.y * 32, n0 = blockIdx.x * 32;
    const int tx = threadIdx.x, ty = threadIdx.y;   // (32, 8)
#pragma unroll
    for (int i = 0; i < 4; ++i)
        t[ty + 8 * i][tx] = W[(size_t)(k0 + ty + 8 * i) * 1024 + n0 + tx];
    __syncthreads();
    __nv_bfloat16* P = g_Ws[WIDX];
    const size_t NK = (size_t)1024 * K;
#pragma unroll
    for (int i = 0; i < 4; ++i) {
        int n = ty + 8 * i;
        float f = t[tx][n];                          // = W[k0+tx][n0+n]
        __nv_bfloat16 b1 = __float2bfloat16(f);
        __nv_bfloat16 b2 = __float2bfloat16(f - __bfloat162float(b1));
        size_t o = (size_t)(n0 + n) * K + k0 + tx;
        P[o] = b1; P[NK + o] = b2;
    }
}

// ---------------------------------------------------------------------------
// wmma bf16x2 GEMM: C[M,1024] = A @ W + bias via 3 split products
// (A1B1 + A1B2 + A2B1) folded into one extended-K loop. Tile 128m x 64n x 32k,
// 8 warps (4m x 2n), HMMA m16n16k16 bf16->f32, double-buffered smem.
// DST 2: head-scatter to g_V; DST 4: plain out.
// ---------------------------------------------------------------------------
template <int DST>
__global__ __launch_bounds__(256, 2) void wmma_gemm(
    const float* __restrict__ bias, float* __restrict__ Cext, int M, int K, int T)
{
    // A: 2 bufs x [128][40] bf16 (10240B); B: 2 bufs x [64][40] (5120B)
    __shared__ __align__(16) unsigned char smraw[30720];
    __shared__ float sbias[64];

    const int tid = threadIdx.x, wid = tid >> 5;
    const int wm = wid & 3, wn = wid >> 2;
    const int n0 = blockIdx.x * 64, m0 = blockIdx.y * 128;

    auto Arow = [&](int buf, int r) -> __nv_bfloat16* {
        return (__nv_bfloat16*)(smraw + buf * 10240 + r * 80);
    };
    auto Brow = [&](int buf, int r) -> __nv_bfloat16* {
        return (__nv_bfloat16*)(smraw + 20480 + buf * 5120 + r * 80);
    };

    if (tid < 64) sbias[tid] = bias[n0 + tid];

    const int WIDX = (DST == 2) ? 0 : 1;
    const __nv_bfloat16* Wt = g_Ws[WIDX];
    const size_t MK = (size_t)M * K, NK = (size_t)1024 * K;
    const int kch = K >> 5, nch = 3 * kch;
    const int PA[3] = {0, 0, 1};
    const int PB[3] = {0, 1, 0};

    wmma::fragment<wmma::accumulator, 16, 16, 16, float> acc[2][2];
#pragma unroll
    for (int i = 0; i < 2; ++i)
#pragma unroll
        for (int j = 0; j < 2; ++j) wmma::fill_fragment(acc[i][j], 0.f);

    {   // prologue: chunk 0 (planes A0/B0, ko=0)
        const __nv_bfloat16* gA = g_Asp + (size_t)m0 * K;
        const __nv_bfloat16* gB = Wt + (size_t)n0 * K;
#pragma unroll
        for (int u = 0; u < 2; ++u) {
            int idx = u * 256 + tid, row = idx >> 2, c8 = idx & 3;
            uint4 v = *(const uint4*)(gA + (size_t)row * K + c8 * 8);
            *(uint4*)(Arow(0, row) + c8 * 8) = v;
        }
        {
            int row = tid >> 2, c8 = tid & 3;
            uint4 v = *(const uint4*)(gB + (size_t)row * K + c8 * 8);
            *(uint4*)(Brow(0, row) + c8 * 8) = v;
        }
    }
    __syncthreads();

    int buf = 0;
    for (int c = 0; c < nch; ++c) {
        uint4 va0, va1, vb;
        const bool has_next = (c + 1) < nch;
        if (has_next) {
            const int cn = c + 1, sub = cn / kch, ko = (cn - sub * kch) << 5;
            const __nv_bfloat16* gA = g_Asp + (size_t)PA[sub] * MK + (size_t)m0 * K + ko;
            const __nv_bfloat16* gB = Wt + (size_t)PB[sub] * NK + (size_t)n0 * K + ko;
            {
                int i0 = tid, r = i0 >> 2, c8 = i0 & 3;
                va0 = *(const uint4*)(gA + (size_t)r * K + c8 * 8);
            }
            {
                int i1 = 256 + tid, r = i1 >> 2, c8 = i1 & 3;
                va1 = *(const uint4*)(gA + (size_t)r * K + c8 * 8);
            }
            {
                int r = tid >> 2, c8 = tid & 3;
                vb = *(const uint4*)(gB + (size_t)r * K + c8 * 8);
            }
        }

#pragma unroll
        for (int ks = 0; ks < 2; ++ks) {
            wmma::fragment<wmma::matrix_a, 16, 16, 16, __nv_bfloat16, wmma::row_major> af[2];
            wmma::fragment<wmma::matrix_b, 16, 16, 16, __nv_bfloat16, wmma::col_major> bf[2];
#pragma unroll
            for (int mi = 0; mi < 2; ++mi)
                wmma::load_matrix_sync(af[mi], Arow(buf, wm * 32 + mi * 16) + ks * 16, 40);
#pragma unroll
            for (int ni = 0; ni < 2; ++ni)
                wmma::load_matrix_sync(bf[ni], Brow(buf, wn * 32 + ni * 16) + ks * 16, 40);
#pragma unroll
            for (int mi = 0; mi < 2; ++mi)
#pragma unroll
                for (int ni = 0; ni < 2; ++ni)
                    wmma::mma_sync(acc[mi][ni], af[mi], bf[ni], acc[mi][ni]);
        }

        if (has_next) {
            const int nb = buf ^ 1;
            {
                int i0 = tid, r = i0 >> 2, c8 = i0 & 3;
                *(uint4*)(Arow(nb, r) + c8 * 8) = va0;
            }
            {
                int i1 = 256 + tid, r = i1 >> 2, c8 = i1 & 3;
                *(uint4*)(Arow(nb, r) + c8 * 8) = va1;
            }
            {
                int r = tid >> 2, c8 = tid & 3;
                *(uint4*)(Brow(nb, r) + c8 * 8) = vb;
            }
            __syncthreads();
            buf = nb;
        }
    }

    // epilogue: two half-passes through smem (reuse smraw as float [128][36])
    float (*Cs)[36] = (float (*)[36])smraw;
    const int r = tid >> 1, hc = (tid & 1) * 16;
    const int m = m0 + r;
    float* dst;
    if (DST == 2) {
        int bb = m / T, tl = m - bb * T, h = n0 >> 6;
        dst = g_V + ((size_t)((bb * Hn + h) * T + tl) << 6);
    } else {
        dst = Cext + (size_t)m * 1024 + n0;
    }

#pragma unroll
    for (int p = 0; p < 2; ++p) {
        __syncthreads();
        if (wn == p) {
#pragma unroll
            for (int mi = 0; mi < 2; ++mi)
#pragma unroll
                for (int ni = 0; ni < 2; ++ni)
                    wmma::store_matrix_sync(&Cs[wm * 32 + mi * 16][ni * 16],
                                            acc[mi][ni], 36, wmma::mem_row_major);
        }
        __syncthreads();
#pragma unroll
        for (int j4 = 0; j4 < 4; ++j4) {
            int cc = hc + j4 * 4;
            float4 v;
            v.x = Cs[r][cc + 0] + sbias[p * 32 + cc + 0];
            v.y = Cs[r][cc + 1] + sbias[p * 32 + cc + 1];
            v.z = Cs[r][cc + 2] + sbias[p * 32 + cc + 2];
            v.w = Cs[r][cc + 3] + sbias[p * 32 + cc + 3];
            *(float4*)(dst + p * 32 + cc) = v;
        }
    }
}

// ---------------------------------------------------------------------------
// QK^T logits GEMM (bitwise-identical to rounds 4-10)
// ---------------------------------------------------------------------------
__global__ __launch_bounds__(256, 2) void qk_logits_k(const void* __restrict__ mask)
{
    extern __shared__ float sm[];
    float (*Qs)[132] = (float (*)[132])sm;
    float (*Ks)[132] = (float (*)[132])(sm + 64 * 132);

    const int tid = threadIdx.x;
    const int bh = blockIdx.z;
    const int q0 = blockIdx.y * 128, n0 = blockIdx.x * 128;
    const float* Qb = g_Q + ((size_t)bh * TQn + q0) * 64;
    const float* Kb = g_K + ((size_t)bh * TKn + n0) * 64;

    {
        const int m = tid & 127, half = tid >> 7;
#pragma unroll
        for (int cc = 0; cc < 8; ++cc) {
            const int d4 = half + 2 * cc;
            float4 qv = *(const float4*)(Qb + (size_t)m * 64 + d4 * 4);
            Qs[d4 * 4 + 0][m] = qv.x * 0.125f;
            Qs[d4 * 4 + 1][m] = qv.y * 0.125f;
            Qs[d4 * 4 + 2][m] = qv.z * 0.125f;
            Qs[d4 * 4 + 3][m] = qv.w * 0.125f;
            float4 kv = *(const float4*)(Kb + (size_t)m * 64 + d4 * 4);
            Ks[d4 * 4 + 0][m] = kv.x;
            Ks[d4 * 4 + 1][m] = kv.y;
            Ks[d4 * 4 + 2][m] = kv.z;
            Ks[d4 * 4 + 3][m] = kv.w;
        }
    }
    __syncthreads();

    const int tx = tid & 15, ty = tid >> 4;
    unsigned long long acc2[8][4];
#pragma unroll
    for (int i = 0; i < 8; ++i)
#pragma unroll
        for (int jp = 0; jp < 4; ++jp) acc2[i][jp] = 0ull;

#pragma unroll 8
    for (int kk = 0; kk < 64; ++kk) {
        float4 a0 = *(const float4*)&Qs[kk][ty * 8];
        float4 a1 = *(const float4*)&Qs[kk][ty * 8 + 4];
        ulonglong2 b01 = *(const ulonglong2*)&Ks[kk][tx * 8];
        ulonglong2 b23 = *(const ulonglong2*)&Ks[kk][tx * 8 + 4];
        unsigned long long b2[4] = {b01.x, b01.y, b23.x, b23.y};
        float ar[8] = {a0.x, a0.y, a0.z, a0.w, a1.x, a1.y, a1.z, a1.w};
#pragma unroll
        for (int i = 0; i < 8; ++i) {
            unsigned long long pa = pack2(ar[i]);
#pragma unroll
            for (int jp = 0; jp < 4; ++jp) FFMA2(acc2[i][jp], pa, b2[jp]);
        }
    }

    const int mode = g_mask_mode, b = bh >> 4;
    unsigned char mku[8];
#pragma unroll
    for (int j = 0; j < 8; ++j) mku[j] = mask_at(mask, mode, b * TKn + n0 + tx * 8 + j);

#pragma unroll
    for (int i = 0; i < 8; ++i) {
        float* Lp = g_L + ((size_t)bh * TQn + q0 + ty * 8 + i) * TKn + n0 + tx * 8;
        float o[8];
#pragma unroll
        for (int jp = 0; jp < 4; ++jp) unpack2(acc2[i][jp], o[2 * jp], o[2 * jp + 1]);
#pragma unroll
        for (int j = 0; j < 8; ++j) if (mku[j]) o[j] = NEG_BIG;
        __stcs((float4*)Lp,       make_float4(o[0], o[1], o[2], o[3]));
        __stcs((float4*)(Lp + 4), make_float4(o[4], o[5], o[6], o[7]));
    }
}

// ---------------------------------------------------------------------------
// Top-64 + softmax + sparse AV. Warp per query.
// Threshold via log-count interpolation (selection-set invariant: exits only
// at cnt==64 or tie-degenerate interval collapse, same as bisection).
// AV with float2 lanes (dims 2*lane, 2*lane+1); epilogue writes bf16x2
// split planes directly (identical arithmetic to the old split_A pass).
// ---------------------------------------------------------------------------
__device__ __forceinline__ int cnt_ge(const float (&a)[64], float t)
{
    int c = 0;
#pragma unroll
    for (int j = 0; j < 64; ++j) c += (a[j] >= t) ? 1 : 0;
    return __reduce_add_sync(0xffffffffu, c);
}

__global__ __launch_bounds__(256, 2) void topk_av_k()
{
    __shared__ int   skey[8][80];
    __shared__ float swgt[8][80];

    const int lane = threadIdx.x & 31, w = threadIdx.x >> 5;
    const int b = blockIdx.z, h = blockIdx.y;
    const int bh = b * Hn + h;
    const int q = blockIdx.x * 8 + w;

    const float* Lq = g_L + ((size_t)bh * TQn + q) * TKn;
    float acc[64];
#pragma unroll
    for (int j = 0; j < 64; ++j) acc[j] = __ldcs(Lq + j * 32 + lane);

    float m = NEG_BIG;
#pragma unroll
    for (int j = 0; j < 64; ++j) m = fmaxf(m, acc[j]);
#pragma unroll
    for (int o = 16; o > 0; o >>= 1) m = fmaxf(m, __shfl_xor_sync(0xffffffffu, m, o));

    // bracketing: lo has cnt>=64, hi has cnt<64 (hi=m assumed cnt~1)
    float lo = m - 32.0f, hi = m;
    int clo = cnt_ge(acc, lo), chi = 1;
    int guard = 0;
    while (clo < 64 && guard++ < 90) { lo = m - 2.0f * (m - lo); clo = cnt_ge(acc, lo); }

    for (int it = 0; it < 32 && clo != 64; ++it) {
        float t;
        if (it == 0) {
            t = m - 1.9f;                    // expected 64th-order-stat offset for ~N(0,1) logits
        } else {
            // log-count interpolation between (hi, chi<64) and (lo, clo>64)
            float f = (__logf(64.f) - __logf((float)chi)) /
                      (__logf((float)clo) - __logf((float)chi));
            t = hi + f * (lo - hi);
        }
        if (!(t > lo && t < hi)) t = 0.5f * (lo + hi);
        if (!(t > lo && t < hi)) break;      // interval collapsed (ties) -> thr=lo
        int c2 = cnt_ge(acc, t);
        if (c2 >= 64) { lo = t; clo = c2; } else { hi = t; chi = c2; }
    }
    const float thr = lo;

    // ballot-prefix compaction of selected (key, exp(logit-m)) pairs
    int base = 0;
#pragma unroll
    for (int j = 0; j < 64; ++j) {
        bool sel = acc[j] >= thr;
        unsigned bal = __ballot_sync(0xffffffffu, sel);
        if (sel) {
            int pos = base + __popc(bal & ((1u << lane) - 1u));
            if (pos < 80) {
                skey[w][pos] = j * 32 + lane;
                swgt[w][pos] = __expf(acc[j] - m);
            }
        }
        base += __popc(bal);
    }
    const int nsel = base < 80 ? base : 80;
    __syncwarp();

    float z = 0.f;
    for (int i = lane; i < nsel; i += 32) z += swgt[w][i];
#pragma unroll
    for (int o = 16; o > 0; o >>= 1) z += __shfl_xor_sync(0xffffffffu, z, o);

    // dense AV: lane owns dims 2*lane, 2*lane+1 (float2 rows); 8-way MLP
    const float* Vb = g_V + (size_t)bh * TKn * 64;
    float o0 = 0.f, o1 = 0.f;
    int i = 0;
    for (; i + 8 <= nsel; i += 8) {
        int   kv[8]; float wv[8];
#pragma unroll
        for (int u = 0; u < 8; ++u) { kv[u] = skey[w][i + u]; wv[u] = swgt[w][i + u]; }
        float2 vv[8];
#pragma unroll
        for (int u = 0; u < 8; ++u)
            vv[u] = *(const float2*)(Vb + (size_t)kv[u] * 64 + 2 * lane);
#pragma unroll
        for (int u = 0; u < 8; ++u) { o0 += wv[u] * vv[u].x; o1 += wv[u] * vv[u].y; }
    }
    for (; i < nsel; ++i) {
        float wv = swgt[w][i];
        float2 vv = *(const float2*)(Vb + (size_t)skey[w][i] * 64 + 2 * lane);
        o0 += wv * vv.x;
        o1 += wv * vv.y;
    }

    // epilogue: normalized output -> bf16x2 split planes (fused old split_A)
    const float inv = 1.0f / z;
    const float r0 = o0 * inv, r1 = o1 * inv;
    __nv_bfloat16 x1 = __float2bfloat16(r0);
    __nv_bfloat16 x2 = __float2bfloat16(r0 - __bfloat162float(x1));
    __nv_bfloat16 y1 = __float2bfloat16(r1);
    __nv_bfloat16 y2 = __float2bfloat16(r1 - __bfloat162float(y1));
    const size_t MK = (size_t)Bb * TQn * DQn;     // AO-plane stride (2048*1024)
    const size_t o = ((size_t)(b * TQn + q)) * DQn + h * 64 + 2 * lane;
    *(__nv_bfloat162*)(g_Asp + o)      = __nv_bfloat162(x1, y1);
    *(__nv_bfloat162*)(g_Asp + MK + o) = __nv_bfloat162(x2, y2);
}

// ---------------------------------------------------------------------------
extern "C" void kernel_launch(void* const* d_in, const int* in_sizes, int n_in,
                              void* d_out, int out_size)
{
    const float* x   = (const float*)d_in[0];
    const float* ctx = (const float*)d_in[1];
    const void*  msk = d_in[2];
    const float* Wq = (const float*)d_in[3];
    const float* bq = (const float*)d_in[4];
    const float* Wk = (const float*)d_in[5];
    const float* bk = (const float*)d_in[6];
    const float* Wv = (const float*)d_in[7];
    const float* bv = (const float*)d_in[8];
    const float* Wo = (const float*)d_in[9];
    const float* bo = (const float*)d_in[10];
    float* out = (float*)d_out;

    const int qk_smem = 2 * 64 * 132 * sizeof(float);   // 67.6 KB
    static bool attr_done = false;
    if (!attr_done) {
        cudaFuncSetAttribute(qk_logits_k, cudaFuncAttributeMaxDynamicSharedMemorySize, qk_smem);
        attr_done = true;
    }

    detect_mask_kernel<<<1, 256>>>((const unsigned char*)msk);

    // Q, K projections: exact fp32 path (selection-critical)
    gemm_k<0><<<dim3(DQn / 128, (Bb * TQn) / 128), 256>>>(x,   Wq, bq, Bb * TQn, DQn, DQn, TQn);
    gemm_k<1><<<dim3(DQn / 128, (Bb * TKn) / 128), 256>>>(ctx, Wk, bk, Bb * TKn, DCn, DQn, TKn);

    // V projection: wmma bf16x2 (selection-independent)
    split_W_k<0><<<dim3(32, 24), dim3(32, 8)>>>(Wv, 768);
    split_W_k<1><<<dim3(32, 32), dim3(32, 8)>>>(Wo, 1024);
    split_A_k<<<4096, 256>>>(ctx, (size_t)4096 * 768);
    wmma_gemm<2><<<dim3(16, 32), 256>>>(bv, nullptr, 4096, 768, 2048);

    // masked logits (bitwise-identical to round 6)
    qk_logits_k<<<dim3(TKn / 128, TQn / 128, Bb * Hn), 256, qk_smem>>>(msk);
    // top-64 + softmax + sparse AV (writes bf16 split planes directly)
    topk_av_k<<<dim3(TQn / 8, Hn, Bb), 256>>>();

    // output projection: wmma bf16x2 (reads planes written by topk_av_k)
    wmma_gemm<4><<<dim3(16, 16), 256>>>(bo, out, 2048, 1024, 1024);
}